// round 1
// baseline (speedup 1.0000x reference)
#include <cuda_runtime.h>
#include <cuda_bf16.h>
#include <cstdint>

#define N_NODES 51200
#define N_EDGES 614400
#define ORIG    92
#define AFL     64
#define BINS    100
#define NCONV   3
#define TBL     4096
#define FCO     128      // 2*AFL
#define EPS_BN  1e-5f
#define PROJ_ROWS 16

// ---------------- device scratch (static, no allocations) ----------------
__device__ float g_h[N_NODES * AFL];          // current node features (13 MB)
__device__ float g_Zd[N_NODES * FCO];         // h @ fcW[0:64]   (26 MB)
__device__ float g_Zs[N_NODES * FCO];         // h @ fcW[64:128] (26 MB)
__device__ float g_M[BINS * FCO];             // lut @ fcW[128:192]
__device__ float g_T[TBL * FCO];              // edge-feature lookup table (2 MB)
__device__ float g_zbuf[(size_t)N_EDGES * FCO]; // z scratch (314 MB)
__device__ float g_aggr[N_NODES * AFL];       // scatter target (13 MB)
__device__ float g_bn1s[FCO];
__device__ float g_bn1q[FCO];
__device__ float g_bn2s[AFL];
__device__ float g_bn2q[AFL];

// ---------------- tiny utility kernels ----------------
__global__ void k_zero_out(float* __restrict__ out, int n) {
    int i = blockIdx.x * blockDim.x + threadIdx.x;
    for (; i < n; i += gridDim.x * blockDim.x) out[i] = 0.f;
}

__global__ void k_zero_layer() {
    int i = blockIdx.x * blockDim.x + threadIdx.x;
    const int total = N_NODES * AFL;
    for (int j = i; j < total; j += gridDim.x * blockDim.x) g_aggr[j] = 0.f;
    if (i < FCO) { g_bn1s[i] = 0.f; g_bn1q[i] = 0.f; }
    if (i < AFL) { g_bn2s[i] = 0.f; g_bn2q[i] = 0.f; }
}

// ---------------- embedding: h = (x*attention) @ emb_W + emb_b ----------------
__global__ void __launch_bounds__(64) k_embed(
    const float* __restrict__ x, const float* __restrict__ att,
    const float* __restrict__ W, const float* __restrict__ b)
{
    __shared__ float xs[ORIG];
    int n = blockIdx.x;
    int c = threadIdx.x;            // 64
    for (int k = c; k < ORIG; k += 64) xs[k] = x[n * ORIG + k] * att[k];
    __syncthreads();
    float acc = b[c];
#pragma unroll 4
    for (int k = 0; k < ORIG; k++) acc = fmaf(xs[k], W[k * AFL + c], acc);
    g_h[n * AFL + c] = acc;
}

// ---------------- per-layer precompute: M = lut @ fcW[128:192] ----------------
__global__ void __launch_bounds__(FCO) k_prepM(
    const float* __restrict__ lut, const float* __restrict__ fcW)
{
    int j = blockIdx.x;             // BINS
    int c = threadIdx.x;            // FCO
    float acc = 0.f;
#pragma unroll 4
    for (int m = 0; m < AFL; m++)
        acc = fmaf(lut[j * AFL + m], fcW[(2 * AFL + m) * FCO + c], acc);
    g_M[j * FCO + c] = acc;
}

// ---------------- per-layer table: T[t] = softmax(v3(a_t)) @ M + fcb ----------------
__global__ void __launch_bounds__(FCO) k_table(
    const float* __restrict__ w1, const float* __restrict__ b1,
    const float* __restrict__ w2, const float* __restrict__ b2,
    const float* __restrict__ alpha, const float* __restrict__ fcb)
{
    __shared__ float v2[BINS];
    __shared__ float p[BINS];
    __shared__ float redA[4];
    __shared__ float redB[4];
    int tid = threadIdx.x;          // 128
    float a = (float)blockIdx.x / (float)(TBL - 1);

    if (tid < BINS) {
        float v = fmaf(a, w1[tid], b1[tid]);
        v2[tid] = v > 0.f ? v : 0.01f * v;      // leaky_relu(0.01)
    }
    __syncthreads();

    float v3 = -3.0e38f;
    if (tid < BINS) {
        float acc = fmaf(alpha[0], v2[tid], b2[tid]);
#pragma unroll 4
        for (int k = 0; k < BINS; k++) acc = fmaf(v2[k], w2[k * BINS + tid], acc);
        v3 = acc;
    }
    // block max (4 warps)
    float m = v3;
#pragma unroll
    for (int o = 16; o; o >>= 1) m = fmaxf(m, __shfl_xor_sync(0xffffffffu, m, o));
    if ((tid & 31) == 0) redA[tid >> 5] = m;
    __syncthreads();
    m = fmaxf(fmaxf(redA[0], redA[1]), fmaxf(redA[2], redA[3]));

    float ex = (tid < BINS) ? expf(v3 - m) : 0.f;
    float s = ex;
#pragma unroll
    for (int o = 16; o; o >>= 1) s += __shfl_xor_sync(0xffffffffu, s, o);
    if ((tid & 31) == 0) redB[tid >> 5] = s;
    __syncthreads();
    s = (redB[0] + redB[1]) + (redB[2] + redB[3]);
    float inv = 1.f / s;
    if (tid < BINS) p[tid] = ex * inv;
    __syncthreads();

    float acc = fcb[tid];
#pragma unroll 4
    for (int j = 0; j < BINS; j++) acc = fmaf(p[j], g_M[j * FCO + tid], acc);
    g_T[blockIdx.x * FCO + tid] = acc;
}

// ---------------- node projections: Zd/Zs = h @ fcW_half  ----------------
__global__ void __launch_bounds__(FCO) k_proj(const float* __restrict__ fcW)
{
    __shared__ float Wsh[AFL * FCO];            // 32 KB
    __shared__ float hsh[AFL][PROJ_ROWS];       // transposed tile, 4 KB
    int c = threadIdx.x;                        // 128
    int half = blockIdx.y;
    const float* Wsrc = fcW + half * AFL * FCO;
    for (int i = c; i < AFL * FCO; i += FCO) Wsh[i] = Wsrc[i];
    int r0 = blockIdx.x * PROJ_ROWS;
    for (int i = c; i < PROJ_ROWS * AFL; i += FCO) {
        int r = i >> 6, k = i & 63;
        hsh[k][r] = g_h[(r0 + r) * AFL + k];
    }
    __syncthreads();

    float acc[PROJ_ROWS];
#pragma unroll
    for (int r = 0; r < PROJ_ROWS; r++) acc[r] = 0.f;

#pragma unroll 4
    for (int k = 0; k < AFL; k++) {
        float w = Wsh[k * FCO + c];
        const float4* hv = reinterpret_cast<const float4*>(&hsh[k][0]);
#pragma unroll
        for (int q = 0; q < PROJ_ROWS / 4; q++) {
            float4 h4 = hv[q];
            acc[q * 4 + 0] = fmaf(h4.x, w, acc[q * 4 + 0]);
            acc[q * 4 + 1] = fmaf(h4.y, w, acc[q * 4 + 1]);
            acc[q * 4 + 2] = fmaf(h4.z, w, acc[q * 4 + 2]);
            acc[q * 4 + 3] = fmaf(h4.w, w, acc[q * 4 + 3]);
        }
    }
    float* dst = half ? g_Zs : g_Zd;
#pragma unroll
    for (int r = 0; r < PROJ_ROWS; r++) dst[(r0 + r) * FCO + c] = acc[r];
}

// ---------------- pass C: z = Zd[dst]+Zs[src]+lerp(T,a); store + BN1 stats ----------------
__global__ void __launch_bounds__(256) k_edge_stats(
    const int* __restrict__ ei, const float* __restrict__ ea)
{
    __shared__ float s_sum[2 * FCO];
    __shared__ float s_sq[2 * FCO];
    int c = threadIdx.x;            // 128
    int ey = threadIdx.y;           // 2
    float psum = 0.f, psq = 0.f;
    for (int e = blockIdx.x * 2 + ey; e < N_EDGES; e += gridDim.x * 2) {
        int src = ei[e];
        int dst = ei[N_EDGES + e];
        float a = ea[e];
        float pos = a * (float)(TBL - 1);
        pos = fminf(fmaxf(pos, 0.f), (float)(TBL - 1));
        int t0 = min((int)pos, TBL - 2);
        float w = pos - (float)t0;
        float T0 = g_T[t0 * FCO + c];
        float T1 = g_T[(t0 + 1) * FCO + c];
        float z = g_Zd[dst * FCO + c] + g_Zs[src * FCO + c] + fmaf(w, T1 - T0, T0);
        g_zbuf[(size_t)e * FCO + c] = z;
        psum += z;
        psq = fmaf(z, z, psq);
    }
    s_sum[ey * FCO + c] = psum;
    s_sq[ey * FCO + c] = psq;
    __syncthreads();
    if (ey == 0) {
        atomicAdd(&g_bn1s[c], s_sum[c] + s_sum[FCO + c]);
        atomicAdd(&g_bn1q[c], s_sq[c] + s_sq[FCO + c]);
    }
}

// ---------------- pass D: normalize, msg = relu*relu, scatter-add ----------------
__global__ void __launch_bounds__(256) k_msg(
    const int* __restrict__ ei,
    const float* __restrict__ g1, const float* __restrict__ b1)
{
    int c = threadIdx.x;            // 64
    int ey = threadIdx.y;           // 4
    const float invE = 1.f / (float)N_EDGES;
    // filter column c
    float mu_f = g_bn1s[c] * invE;
    float var_f = g_bn1q[c] * invE - mu_f * mu_f;
    float sc_f = rsqrtf(var_f + EPS_BN) * g1[c];
    float sh_f = fmaf(-mu_f, sc_f, b1[c]);
    // core column c+64
    float mu_c = g_bn1s[AFL + c] * invE;
    float var_c = g_bn1q[AFL + c] * invE - mu_c * mu_c;
    float sc_c = rsqrtf(var_c + EPS_BN) * g1[AFL + c];
    float sh_c = fmaf(-mu_c, sc_c, b1[AFL + c]);

    for (int e = blockIdx.x * 4 + ey; e < N_EDGES; e += gridDim.x * 4) {
        int dst = ei[N_EDGES + e];
        size_t base = (size_t)e * FCO;
        float f = fmaf(g_zbuf[base + c], sc_f, sh_f);
        float g = fmaf(g_zbuf[base + AFL + c], sc_c, sh_c);
        float m = fmaxf(f, 0.f) * fmaxf(g, 0.f);
        atomicAdd(&g_aggr[dst * AFL + c], m);
    }
}

// ---------------- bn2 stats over aggr ----------------
__global__ void __launch_bounds__(AFL) k_aggr_stats()
{
    int c = threadIdx.x;            // 64
    float ps = 0.f, pq = 0.f;
    for (int n = blockIdx.x; n < N_NODES; n += gridDim.x) {
        float v = g_aggr[n * AFL + c];
        ps += v;
        pq = fmaf(v, v, pq);
    }
    atomicAdd(&g_bn2s[c], ps);
    atomicAdd(&g_bn2q[c], pq);
}

// ---------------- h = relu(h + bn2(aggr)) ----------------
__global__ void __launch_bounds__(256) k_update(
    const float* __restrict__ g2, const float* __restrict__ b2)
{
    int c = threadIdx.x;            // 64
    int ey = threadIdx.y;           // 4
    const float invN = 1.f / (float)N_NODES;
    float mu = g_bn2s[c] * invN;
    float var = g_bn2q[c] * invN - mu * mu;
    float sc = rsqrtf(var + EPS_BN) * g2[c];
    float sh = fmaf(-mu, sc, b2[c]);
    for (int n = blockIdx.x * 4 + ey; n < N_NODES; n += gridDim.x * 4) {
        float v = fmaf(g_aggr[n * AFL + c], sc, sh) + g_h[n * AFL + c];
        g_h[n * AFL + c] = fmaxf(v, 0.f);
    }
}

// ---------------- pooling: out[batch] += softmax(h @ ppW + ppb) ----------------
__global__ void __launch_bounds__(AFL) k_pool(
    const float* __restrict__ ppW, const float* __restrict__ ppb,
    float* __restrict__ out, const int* __restrict__ bs)
{
    __shared__ float hs[AFL];
    __shared__ float redA[2];
    __shared__ float redB[2];
    int n = blockIdx.x;
    int c = threadIdx.x;            // 64
    hs[c] = g_h[n * AFL + c];
    __syncthreads();
    float acc = ppb[c];
#pragma unroll 4
    for (int k = 0; k < AFL; k++) acc = fmaf(hs[k], ppW[k * AFL + c], acc);
    float m = acc;
#pragma unroll
    for (int o = 16; o; o >>= 1) m = fmaxf(m, __shfl_xor_sync(0xffffffffu, m, o));
    if ((c & 31) == 0) redA[c >> 5] = m;
    __syncthreads();
    m = fmaxf(redA[0], redA[1]);
    float ex = expf(acc - m);
    float s = ex;
#pragma unroll
    for (int o = 16; o; o >>= 1) s += __shfl_xor_sync(0xffffffffu, s, o);
    if ((c & 31) == 0) redB[c >> 5] = s;
    __syncthreads();
    s = redB[0] + redB[1];
    int numAtom = N_NODES / bs[0];
    atomicAdd(&out[(n / numAtom) * AFL + c], ex / s);
}

// ---------------- launch ----------------
extern "C" void kernel_launch(void* const* d_in, const int* in_sizes, int n_in,
                              void* d_out, int out_size)
{
    const float* x     = (const float*)d_in[0];
    const int*   ei    = (const int*)  d_in[1];
    const float* ea    = (const float*)d_in[2];
    const int*   bs    = (const int*)  d_in[3];
    const float* att   = (const float*)d_in[4];
    const float* embW  = (const float*)d_in[5];
    const float* embb  = (const float*)d_in[6];
    const float* adw1  = (const float*)d_in[7];
    const float* adb1  = (const float*)d_in[8];
    const float* adw2  = (const float*)d_in[9];
    const float* adb2  = (const float*)d_in[10];
    const float* adal  = (const float*)d_in[11];
    const float* adlut = (const float*)d_in[12];
    const float* fcW   = (const float*)d_in[13];
    const float* fcb   = (const float*)d_in[14];
    const float* bn1g  = (const float*)d_in[15];
    const float* bn1b  = (const float*)d_in[16];
    const float* bn2g  = (const float*)d_in[17];
    const float* bn2b  = (const float*)d_in[18];
    const float* ppW   = (const float*)d_in[19];
    const float* ppb   = (const float*)d_in[20];
    float* out = (float*)d_out;

    k_zero_out<<<16, 256>>>(out, out_size);
    k_embed<<<N_NODES, 64>>>(x, att, embW, embb);
    k_pool<<<N_NODES, AFL>>>(ppW, ppb, out, bs);

    for (int l = 0; l < NCONV; l++) {
        k_prepM<<<BINS, FCO>>>(adlut + l * BINS * AFL, fcW + l * (3 * AFL) * FCO);
        k_table<<<TBL, FCO>>>(adw1 + l * BINS, adb1 + l * BINS,
                              adw2 + l * BINS * BINS, adb2 + l * BINS,
                              adal + l, fcb + l * FCO);
        dim3 pg(N_NODES / PROJ_ROWS, 2);
        k_proj<<<pg, FCO>>>(fcW + l * (3 * AFL) * FCO);
        k_zero_layer<<<1024, 256>>>();
        k_edge_stats<<<2048, dim3(FCO, 2)>>>(ei, ea);
        k_msg<<<2048, dim3(AFL, 4)>>>(ei, bn1g + l * FCO, bn1b + l * FCO);
        k_aggr_stats<<<512, AFL>>>();
        k_update<<<512, dim3(AFL, 4)>>>(bn2g + l * AFL, bn2b + l * AFL);
        k_pool<<<N_NODES, AFL>>>(ppW, ppb, out, bs);
    }
}

// round 2
// speedup vs baseline: 1.1249x; 1.1249x over previous
#include <cuda_runtime.h>
#include <cuda_bf16.h>
#include <cstdint>

#define N_NODES 51200
#define N_EDGES 614400
#define ORIG    92
#define AFL     64
#define BINS    100
#define NCONV   3
#define TBL     512
#define FCO     128      // 2*AFL
#define EPS_BN  1e-5f
#define PROJ_ROWS 16
#define EGRID   1024     // blocks for edge pass C
#define DGRID   1024     // blocks for edge pass D

// ---------------- device scratch (static, no allocations) ----------------
__device__ float g_h[N_NODES * AFL];          // current node features (13 MB)
__device__ float g_Zd[N_NODES * FCO];         // h @ fcW[0:64]   (26 MB)
__device__ float g_Zs[N_NODES * FCO];         // h @ fcW[64:128] (26 MB)
__device__ float g_M[BINS * FCO];             // lut @ fcW[128:192]
__device__ float g_T[TBL * FCO];              // edge-feature lookup table (256 KB)
__device__ float g_aggr[N_NODES * AFL];       // per-node aggregation (13 MB)
__device__ float g_part1[EGRID * 256];        // BN1 partials (sum128 | sq128)
__device__ float g_part2[DGRID * 128];        // BN2 partials (sum64 | sq64)
__device__ float g_bn1sc[FCO], g_bn1sh[FCO];
__device__ float g_bn2sc[AFL], g_bn2sh[AFL];
// edge sort (built once per launch, reused by all layers)
__device__ int   g_cnt[N_NODES];
__device__ int   g_bsum[256];
__device__ int   g_segstart[N_NODES + 1];
__device__ int   g_off[N_NODES];
__device__ int   g_psrc[N_EDGES];
__device__ float g_pattr[N_EDGES];

// ---------------- misc ----------------
__global__ void k_zero_out(float* __restrict__ out, int n) {
    int i = blockIdx.x * blockDim.x + threadIdx.x;
    for (; i < n; i += gridDim.x * blockDim.x) out[i] = 0.f;
}

// ---------------- edge sort: counting sort by dst ----------------
__global__ void k_zero_cnt() {
    int i = blockIdx.x * blockDim.x + threadIdx.x;
    for (; i < N_NODES; i += gridDim.x * blockDim.x) g_cnt[i] = 0;
}

__global__ void __launch_bounds__(1024) k_hist(const int* __restrict__ ei) {
    int e = blockIdx.x * blockDim.x + threadIdx.x;
    if (e < N_EDGES) atomicAdd(&g_cnt[ei[N_EDGES + e]], 1);
}

__global__ void __launch_bounds__(256) k_bsum() {
    __shared__ int sh[8];
    int b = blockIdx.x, t = threadIdx.x;
    int v = g_cnt[b * 256 + t];
#pragma unroll
    for (int o = 16; o; o >>= 1) v += __shfl_xor_sync(0xffffffffu, v, o);
    if ((t & 31) == 0) sh[t >> 5] = v;
    __syncthreads();
    if (t == 0) {
        int s = 0;
#pragma unroll
        for (int w = 0; w < 8; w++) s += sh[w];
        g_bsum[b] = s;
    }
}

__global__ void __launch_bounds__(256) k_scan_b() {
    __shared__ int sh[256];
    int t = threadIdx.x;
    int own = (t < 200) ? g_bsum[t] : 0;
    sh[t] = own;
    __syncthreads();
#pragma unroll
    for (int o = 1; o < 256; o <<= 1) {
        int v = (t >= o) ? sh[t - o] : 0;
        __syncthreads();
        sh[t] += v;
        __syncthreads();
    }
    if (t < 200) g_bsum[t] = sh[t] - own;   // exclusive
    if (t == 0) g_segstart[N_NODES] = N_EDGES;
}

__global__ void __launch_bounds__(256) k_scan_local() {
    __shared__ int sh[256];
    int b = blockIdx.x, t = threadIdx.x;
    int own = g_cnt[b * 256 + t];
    sh[t] = own;
    __syncthreads();
#pragma unroll
    for (int o = 1; o < 256; o <<= 1) {
        int v = (t >= o) ? sh[t - o] : 0;
        __syncthreads();
        sh[t] += v;
        __syncthreads();
    }
    int beg = g_bsum[b] + sh[t] - own;       // exclusive
    g_segstart[b * 256 + t] = beg;
    g_off[b * 256 + t] = beg;
}

__global__ void __launch_bounds__(1024) k_scatter(const int* __restrict__ ei,
                                                  const float* __restrict__ ea) {
    int e = blockIdx.x * blockDim.x + threadIdx.x;
    if (e < N_EDGES) {
        int dst = ei[N_EDGES + e];
        int pos = atomicAdd(&g_off[dst], 1);
        g_psrc[pos] = ei[e];
        g_pattr[pos] = ea[e];
    }
}

// ---------------- embedding + initial pooling (fused) ----------------
__global__ void __launch_bounds__(256) k_embed_pool(
    const float* __restrict__ x, const float* __restrict__ att,
    const float* __restrict__ W, const float* __restrict__ b,
    const float* __restrict__ ppW, const float* __restrict__ ppb,
    float* __restrict__ out, const int* __restrict__ bs)
{
    __shared__ float Ws[ORIG * AFL];     // 23.5 KB
    __shared__ float ppWs[AFL * AFL];    // 16 KB
    __shared__ float xs[4][ORIG];
    __shared__ float hs[4][AFL];
    __shared__ float red[8];
    int tid = threadIdx.x;
    int g = tid >> 6, c = tid & 63;
    int n = blockIdx.x * 4 + g;
    for (int i = tid; i < ORIG * AFL; i += 256) Ws[i] = W[i];
    for (int i = tid; i < AFL * AFL; i += 256) ppWs[i] = ppW[i];
    for (int i = tid; i < 4 * ORIG; i += 256) {
        int gg = i / ORIG, k = i % ORIG;
        xs[gg][k] = x[(blockIdx.x * 4 + gg) * ORIG + k] * att[k];
    }
    __syncthreads();
    float acc = b[c];
#pragma unroll 4
    for (int k = 0; k < ORIG; k++) acc = fmaf(xs[g][k], Ws[k * AFL + c], acc);
    g_h[n * AFL + c] = acc;
    hs[g][c] = acc;
    __syncthreads();
    float p = ppb[c];
#pragma unroll 8
    for (int k = 0; k < AFL; k++) p = fmaf(hs[g][k], ppWs[k * AFL + c], p);
    // softmax over the 64-thread group (2 warps)
    int wid = tid >> 5;
    float m = p;
#pragma unroll
    for (int o = 16; o; o >>= 1) m = fmaxf(m, __shfl_xor_sync(0xffffffffu, m, o));
    if ((tid & 31) == 0) red[wid] = m;
    __syncthreads();
    m = fmaxf(red[g * 2], red[g * 2 + 1]);
    float ex = expf(p - m);
    float s = ex;
#pragma unroll
    for (int o = 16; o; o >>= 1) s += __shfl_xor_sync(0xffffffffu, s, o);
    __syncthreads();
    if ((tid & 31) == 0) red[wid] = s;
    __syncthreads();
    s = red[g * 2] + red[g * 2 + 1];
    int numAtom = N_NODES / bs[0];
    atomicAdd(&out[(n / numAtom) * AFL + c], ex / s);
}

// ---------------- per-layer precompute: M = lut @ fcW[128:192] ----------------
__global__ void __launch_bounds__(FCO) k_prepM(
    const float* __restrict__ lut, const float* __restrict__ fcW)
{
    int j = blockIdx.x, c = threadIdx.x;
    float acc = 0.f;
#pragma unroll 4
    for (int m = 0; m < AFL; m++)
        acc = fmaf(lut[j * AFL + m], fcW[(2 * AFL + m) * FCO + c], acc);
    g_M[j * FCO + c] = acc;
}

// ---------------- per-layer table: T[t] = softmax(v3(a_t)) @ M + fcb ----------------
__global__ void __launch_bounds__(FCO) k_table(
    const float* __restrict__ w1, const float* __restrict__ b1,
    const float* __restrict__ w2, const float* __restrict__ b2,
    const float* __restrict__ alpha, const float* __restrict__ fcb)
{
    __shared__ float v2[BINS];
    __shared__ float p[BINS];
    __shared__ float redA[4];
    __shared__ float redB[4];
    int tid = threadIdx.x;
    float a = (float)blockIdx.x / (float)(TBL - 1);
    if (tid < BINS) {
        float v = fmaf(a, w1[tid], b1[tid]);
        v2[tid] = v > 0.f ? v : 0.01f * v;
    }
    __syncthreads();
    float v3 = -3.0e38f;
    if (tid < BINS) {
        float acc = fmaf(alpha[0], v2[tid], b2[tid]);
#pragma unroll 4
        for (int k = 0; k < BINS; k++) acc = fmaf(v2[k], w2[k * BINS + tid], acc);
        v3 = acc;
    }
    float m = v3;
#pragma unroll
    for (int o = 16; o; o >>= 1) m = fmaxf(m, __shfl_xor_sync(0xffffffffu, m, o));
    if ((tid & 31) == 0) redA[tid >> 5] = m;
    __syncthreads();
    m = fmaxf(fmaxf(redA[0], redA[1]), fmaxf(redA[2], redA[3]));
    float ex = (tid < BINS) ? expf(v3 - m) : 0.f;
    float s = ex;
#pragma unroll
    for (int o = 16; o; o >>= 1) s += __shfl_xor_sync(0xffffffffu, s, o);
    if ((tid & 31) == 0) redB[tid >> 5] = s;
    __syncthreads();
    s = (redB[0] + redB[1]) + (redB[2] + redB[3]);
    float inv = 1.f / s;
    if (tid < BINS) p[tid] = ex * inv;
    __syncthreads();
    float acc = fcb[tid];
#pragma unroll 4
    for (int j = 0; j < BINS; j++) acc = fmaf(p[j], g_M[j * FCO + tid], acc);
    g_T[blockIdx.x * FCO + tid] = acc;
}

// ---------------- node projections: Zd/Zs = h @ fcW_half ----------------
__global__ void __launch_bounds__(FCO) k_proj(const float* __restrict__ fcW)
{
    __shared__ float Wsh[AFL * FCO];
    __shared__ float hsh[AFL][PROJ_ROWS];
    int c = threadIdx.x;
    int half = blockIdx.y;
    const float* Wsrc = fcW + half * AFL * FCO;
    for (int i = c; i < AFL * FCO; i += FCO) Wsh[i] = Wsrc[i];
    int r0 = blockIdx.x * PROJ_ROWS;
    for (int i = c; i < PROJ_ROWS * AFL; i += FCO) {
        int r = i >> 6, k = i & 63;
        hsh[k][r] = g_h[(r0 + r) * AFL + k];
    }
    __syncthreads();
    float acc[PROJ_ROWS];
#pragma unroll
    for (int r = 0; r < PROJ_ROWS; r++) acc[r] = 0.f;
#pragma unroll 4
    for (int k = 0; k < AFL; k++) {
        float w = Wsh[k * FCO + c];
        const float4* hv = reinterpret_cast<const float4*>(&hsh[k][0]);
#pragma unroll
        for (int q = 0; q < PROJ_ROWS / 4; q++) {
            float4 h4 = hv[q];
            acc[q * 4 + 0] = fmaf(h4.x, w, acc[q * 4 + 0]);
            acc[q * 4 + 1] = fmaf(h4.y, w, acc[q * 4 + 1]);
            acc[q * 4 + 2] = fmaf(h4.z, w, acc[q * 4 + 2]);
            acc[q * 4 + 3] = fmaf(h4.w, w, acc[q * 4 + 3]);
        }
    }
    float* dst = half ? g_Zs : g_Zd;
#pragma unroll
    for (int r = 0; r < PROJ_ROWS; r++) dst[(r0 + r) * FCO + c] = acc[r];
}

// helper: z = zd + zs + lerp(T)
__device__ __forceinline__ float4 edge_z(float4 zd, int src, float a, int lane) {
    float pos = fminf(fmaxf(a * (float)(TBL - 1), 0.f), (float)(TBL - 1));
    int t0 = min((int)pos, TBL - 2);
    float w = pos - (float)t0;
    float4 zs = reinterpret_cast<const float4*>(&g_Zs[(size_t)src * FCO])[lane];
    float4 T0 = reinterpret_cast<const float4*>(&g_T[(size_t)t0 * FCO])[lane];
    float4 T1 = reinterpret_cast<const float4*>(&g_T[(size_t)(t0 + 1) * FCO])[lane];
    float4 z;
    z.x = zd.x + zs.x + fmaf(w, T1.x - T0.x, T0.x);
    z.y = zd.y + zs.y + fmaf(w, T1.y - T0.y, T0.y);
    z.z = zd.z + zs.z + fmaf(w, T1.z - T0.z, T0.z);
    z.w = zd.w + zs.w + fmaf(w, T1.w - T0.w, T0.w);
    return z;
}

// ---------------- pass C: BN1 stats over z (recompute, no store) ----------------
__global__ void __launch_bounds__(256) k_edgeC()
{
    __shared__ float sred[8 * 256];
    int warp = threadIdx.x >> 5, lane = threadIdx.x & 31;
    int gw = blockIdx.x * 8 + warp;
    int nw = gridDim.x * 8;
    float4 ps = {0, 0, 0, 0}, pq = {0, 0, 0, 0};
    for (int n = gw; n < N_NODES; n += nw) {
        int beg = g_segstart[n], end = g_segstart[n + 1];
        if (beg == end) continue;
        float4 zd = reinterpret_cast<const float4*>(&g_Zd[(size_t)n * FCO])[lane];
        for (int base = beg; base < end; base += 32) {
            int e = base + lane;
            int sv = 0; float av = 0.f;
            if (e < end) { sv = g_psrc[e]; av = g_pattr[e]; }
            int cnt = min(32, end - base);
            for (int j = 0; j < cnt; j++) {
                int src = __shfl_sync(0xffffffffu, sv, j);
                float a = __shfl_sync(0xffffffffu, av, j);
                float4 z = edge_z(zd, src, a, lane);
                ps.x += z.x; ps.y += z.y; ps.z += z.z; ps.w += z.w;
                pq.x = fmaf(z.x, z.x, pq.x); pq.y = fmaf(z.y, z.y, pq.y);
                pq.z = fmaf(z.z, z.z, pq.z); pq.w = fmaf(z.w, z.w, pq.w);
            }
        }
    }
    int b = warp * 256 + 4 * lane;
    sred[b + 0] = ps.x; sred[b + 1] = ps.y; sred[b + 2] = ps.z; sred[b + 3] = ps.w;
    sred[b + 128] = pq.x; sred[b + 129] = pq.y; sred[b + 130] = pq.z; sred[b + 131] = pq.w;
    __syncthreads();
    int tid = threadIdx.x;
    float v = 0.f;
#pragma unroll
    for (int w = 0; w < 8; w++) v += sred[w * 256 + tid];
    g_part1[blockIdx.x * 256 + tid] = v;
}

__global__ void __launch_bounds__(256) k_red1(
    const float* __restrict__ g1, const float* __restrict__ b1)
{
    __shared__ float sh[256];
    int tid = threadIdx.x;
    float s = 0.f;
#pragma unroll 4
    for (int b = 0; b < EGRID; b++) s += g_part1[b * 256 + tid];
    sh[tid] = s;
    __syncthreads();
    if (tid < FCO) {
        const float invE = 1.f / (float)N_EDGES;
        float mu = sh[tid] * invE;
        float var = sh[128 + tid] * invE - mu * mu;
        float sc = rsqrtf(var + EPS_BN) * g1[tid];
        g_bn1sc[tid] = sc;
        g_bn1sh[tid] = fmaf(-mu, sc, b1[tid]);
    }
}

// ---------------- pass D: recompute z, BN1, relu*relu, segment-sum + BN2 stats ----------------
__global__ void __launch_bounds__(256) k_edgeD()
{
    __shared__ float sred[8 * 128];
    int warp = threadIdx.x >> 5, lane = threadIdx.x & 31;
    int gw = blockIdx.x * 8 + warp;
    int nw = gridDim.x * 8;
    float4 sc4 = reinterpret_cast<const float4*>(g_bn1sc)[lane];
    float4 sh4 = reinterpret_cast<const float4*>(g_bn1sh)[lane];
    float4 ps = {0, 0, 0, 0}, pq = {0, 0, 0, 0};
    for (int n = gw; n < N_NODES; n += nw) {
        int beg = g_segstart[n], end = g_segstart[n + 1];
        float4 acc = {0, 0, 0, 0};
        if (beg < end) {
            float4 zd = reinterpret_cast<const float4*>(&g_Zd[(size_t)n * FCO])[lane];
            for (int base = beg; base < end; base += 32) {
                int e = base + lane;
                int sv = 0; float av = 0.f;
                if (e < end) { sv = g_psrc[e]; av = g_pattr[e]; }
                int cnt = min(32, end - base);
                for (int j = 0; j < cnt; j++) {
                    int src = __shfl_sync(0xffffffffu, sv, j);
                    float a = __shfl_sync(0xffffffffu, av, j);
                    float4 z = edge_z(zd, src, a, lane);
                    float4 r;
                    r.x = fmaxf(fmaf(z.x, sc4.x, sh4.x), 0.f);
                    r.y = fmaxf(fmaf(z.y, sc4.y, sh4.y), 0.f);
                    r.z = fmaxf(fmaf(z.z, sc4.z, sh4.z), 0.f);
                    r.w = fmaxf(fmaf(z.w, sc4.w, sh4.w), 0.f);
                    float cx = __shfl_down_sync(0xffffffffu, r.x, 16);
                    float cy = __shfl_down_sync(0xffffffffu, r.y, 16);
                    float cz = __shfl_down_sync(0xffffffffu, r.z, 16);
                    float cw = __shfl_down_sync(0xffffffffu, r.w, 16);
                    if (lane < 16) {
                        acc.x = fmaf(r.x, cx, acc.x);
                        acc.y = fmaf(r.y, cy, acc.y);
                        acc.z = fmaf(r.z, cz, acc.z);
                        acc.w = fmaf(r.w, cw, acc.w);
                    }
                }
            }
        }
        if (lane < 16) {
            reinterpret_cast<float4*>(&g_aggr[(size_t)n * AFL])[lane] = acc;
            ps.x += acc.x; ps.y += acc.y; ps.z += acc.z; ps.w += acc.w;
            pq.x = fmaf(acc.x, acc.x, pq.x); pq.y = fmaf(acc.y, acc.y, pq.y);
            pq.z = fmaf(acc.z, acc.z, pq.z); pq.w = fmaf(acc.w, acc.w, pq.w);
        }
    }
    if (lane < 16) {
        int b = warp * 128 + 4 * lane;
        sred[b + 0] = ps.x; sred[b + 1] = ps.y; sred[b + 2] = ps.z; sred[b + 3] = ps.w;
        sred[b + 64] = pq.x; sred[b + 65] = pq.y; sred[b + 66] = pq.z; sred[b + 67] = pq.w;
    }
    __syncthreads();
    int tid = threadIdx.x;
    if (tid < 128) {
        float v = 0.f;
#pragma unroll
        for (int w = 0; w < 8; w++) v += sred[w * 128 + tid];
        g_part2[blockIdx.x * 128 + tid] = v;
    }
}

__global__ void __launch_bounds__(128) k_red2(
    const float* __restrict__ g2, const float* __restrict__ b2)
{
    __shared__ float sh[128];
    int tid = threadIdx.x;
    float s = 0.f;
#pragma unroll 4
    for (int b = 0; b < DGRID; b++) s += g_part2[b * 128 + tid];
    sh[tid] = s;
    __syncthreads();
    if (tid < AFL) {
        const float invN = 1.f / (float)N_NODES;
        float mu = sh[tid] * invN;
        float var = sh[64 + tid] * invN - mu * mu;
        float sc = rsqrtf(var + EPS_BN) * g2[tid];
        g_bn2sc[tid] = sc;
        g_bn2sh[tid] = fmaf(-mu, sc, b2[tid]);
    }
}

// ---------------- h = relu(h + bn2(aggr)); fused softmax pooling ----------------
__global__ void __launch_bounds__(256) k_update_pool(
    const float* __restrict__ ppW, const float* __restrict__ ppb,
    float* __restrict__ out, const int* __restrict__ bs)
{
    __shared__ float ppWs[AFL * AFL];
    __shared__ float hs[4][AFL];
    __shared__ float red[8];
    int tid = threadIdx.x;
    int g = tid >> 6, c = tid & 63;
    int n = blockIdx.x * 4 + g;
    for (int i = tid; i < AFL * AFL; i += 256) ppWs[i] = ppW[i];
    float up = fmaxf(g_h[n * AFL + c] +
                     fmaf(g_aggr[n * AFL + c], g_bn2sc[c], g_bn2sh[c]), 0.f);
    g_h[n * AFL + c] = up;
    hs[g][c] = up;
    __syncthreads();
    float p = ppb[c];
#pragma unroll 8
    for (int k = 0; k < AFL; k++) p = fmaf(hs[g][k], ppWs[k * AFL + c], p);
    int wid = tid >> 5;
    float m = p;
#pragma unroll
    for (int o = 16; o; o >>= 1) m = fmaxf(m, __shfl_xor_sync(0xffffffffu, m, o));
    if ((tid & 31) == 0) red[wid] = m;
    __syncthreads();
    m = fmaxf(red[g * 2], red[g * 2 + 1]);
    float ex = expf(p - m);
    float s = ex;
#pragma unroll
    for (int o = 16; o; o >>= 1) s += __shfl_xor_sync(0xffffffffu, s, o);
    __syncthreads();
    if ((tid & 31) == 0) red[wid] = s;
    __syncthreads();
    s = red[g * 2] + red[g * 2 + 1];
    int numAtom = N_NODES / bs[0];
    atomicAdd(&out[(n / numAtom) * AFL + c], ex / s);
}

// ---------------- launch ----------------
extern "C" void kernel_launch(void* const* d_in, const int* in_sizes, int n_in,
                              void* d_out, int out_size)
{
    const float* x     = (const float*)d_in[0];
    const int*   ei    = (const int*)  d_in[1];
    const float* ea    = (const float*)d_in[2];
    const int*   bs    = (const int*)  d_in[3];
    const float* att   = (const float*)d_in[4];
    const float* embW  = (const float*)d_in[5];
    const float* embb  = (const float*)d_in[6];
    const float* adw1  = (const float*)d_in[7];
    const float* adb1  = (const float*)d_in[8];
    const float* adw2  = (const float*)d_in[9];
    const float* adb2  = (const float*)d_in[10];
    const float* adal  = (const float*)d_in[11];
    const float* adlut = (const float*)d_in[12];
    const float* fcW   = (const float*)d_in[13];
    const float* fcb   = (const float*)d_in[14];
    const float* bn1g  = (const float*)d_in[15];
    const float* bn1b  = (const float*)d_in[16];
    const float* bn2g  = (const float*)d_in[17];
    const float* bn2b  = (const float*)d_in[18];
    const float* ppW   = (const float*)d_in[19];
    const float* ppb   = (const float*)d_in[20];
    float* out = (float*)d_out;

    k_zero_out<<<16, 256>>>(out, out_size);

    // edge sort by dst (reused across all 3 layers)
    k_zero_cnt<<<64, 256>>>();
    k_hist<<<N_EDGES / 1024, 1024>>>(ei);
    k_bsum<<<200, 256>>>();
    k_scan_b<<<1, 256>>>();
    k_scan_local<<<200, 256>>>();
    k_scatter<<<N_EDGES / 1024, 1024>>>(ei, ea);

    k_embed_pool<<<N_NODES / 4, 256>>>(x, att, embW, embb, ppW, ppb, out, bs);

    for (int l = 0; l < NCONV; l++) {
        k_prepM<<<BINS, FCO>>>(adlut + l * BINS * AFL, fcW + l * (3 * AFL) * FCO);
        k_table<<<TBL, FCO>>>(adw1 + l * BINS, adb1 + l * BINS,
                              adw2 + l * BINS * BINS, adb2 + l * BINS,
                              adal + l, fcb + l * FCO);
        dim3 pg(N_NODES / PROJ_ROWS, 2);
        k_proj<<<pg, FCO>>>(fcW + l * (3 * AFL) * FCO);
        k_edgeC<<<EGRID, 256>>>();
        k_red1<<<1, 256>>>(bn1g + l * FCO, bn1b + l * FCO);
        k_edgeD<<<DGRID, 256>>>();
        k_red2<<<1, 128>>>(bn2g + l * AFL, bn2b + l * AFL);
        k_update_pool<<<N_NODES / 4, 256>>>(ppW, ppb, out, bs);
    }
}

// round 3
// speedup vs baseline: 1.2136x; 1.0788x over previous
#include <cuda_runtime.h>
#include <cuda_bf16.h>
#include <cstdint>

#define N_NODES 51200
#define N_EDGES 614400
#define ORIG    92
#define AFL     64
#define BINS    100
#define NCONV   3
#define TBL     128
#define FCO     128      // 2*AFL
#define EPS_BN  1e-5f
#define PROJ_ROWS 32
#define EGRID   1024
#define DGRID   1024

// ---------------- device scratch (static, no allocations) ----------------
__device__ float g_h[N_NODES * AFL];
__device__ float g_Zd[N_NODES * FCO];
__device__ float g_Zs[N_NODES * FCO];
__device__ float g_M[BINS * FCO];
__device__ float g_T[TBL * FCO];              // 64 KB: L1-resident
__device__ float g_aggr[N_NODES * AFL];
__device__ float g_part1[EGRID * 256];
__device__ float g_part2[DGRID * 128];
__device__ float g_bn1sc[FCO], g_bn1sh[FCO];
__device__ float g_bn2sc[AFL], g_bn2sh[AFL];
__device__ int   g_cnt[N_NODES];
__device__ int   g_segstart[N_NODES + 1];
__device__ int   g_off[N_NODES];
__device__ int   g_psrc[N_EDGES];
__device__ float g_pattr[N_EDGES];

// ---------------- zero out + cnt ----------------
__global__ void k_zero(float* __restrict__ out, int n) {
    int i = blockIdx.x * blockDim.x + threadIdx.x;
    int stride = gridDim.x * blockDim.x;
    for (int j = i; j < n; j += stride) out[j] = 0.f;
    for (int j = i; j < N_NODES; j += stride) g_cnt[j] = 0;
}

// ---------------- edge sort ----------------
__global__ void __launch_bounds__(1024) k_hist(const int* __restrict__ ei) {
    int e = blockIdx.x * blockDim.x + threadIdx.x;
    if (e < N_EDGES) atomicAdd(&g_cnt[ei[N_EDGES + e]], 1);
}

__global__ void __launch_bounds__(1024) k_scan() {
    __shared__ int sh[1024];
    __shared__ int carry;
    int tid = threadIdx.x;
    if (tid == 0) carry = 0;
    __syncthreads();
    for (int base = 0; base < N_NODES; base += 1024) {
        int v = g_cnt[base + tid];
        sh[tid] = v;
        __syncthreads();
#pragma unroll
        for (int o = 1; o < 1024; o <<= 1) {
            int u = (tid >= o) ? sh[tid - o] : 0;
            __syncthreads();
            sh[tid] += u;
            __syncthreads();
        }
        int ex = carry + sh[tid] - v;
        g_segstart[base + tid] = ex;
        g_off[base + tid] = ex;
        __syncthreads();
        if (tid == 1023) carry += sh[1023];
        __syncthreads();
    }
    if (tid == 0) g_segstart[N_NODES] = N_EDGES;
}

__global__ void __launch_bounds__(1024) k_scatter(const int* __restrict__ ei,
                                                  const float* __restrict__ ea) {
    int e = blockIdx.x * blockDim.x + threadIdx.x;
    if (e < N_EDGES) {
        int dst = ei[N_EDGES + e];
        int pos = atomicAdd(&g_off[dst], 1);
        g_psrc[pos] = ei[e];
        g_pattr[pos] = ea[e];
    }
}

// ---------------- embedding + initial pooling (8 nodes/block) ----------------
__global__ void __launch_bounds__(512) k_embed_pool(
    const float* __restrict__ x, const float* __restrict__ att,
    const float* __restrict__ W, const float* __restrict__ b,
    const float* __restrict__ ppW, const float* __restrict__ ppb,
    float* __restrict__ out, const int* __restrict__ bs)
{
    __shared__ float Ws[ORIG * AFL];     // 23.5 KB
    __shared__ float ppWs[AFL * AFL];    // 16 KB
    __shared__ float xs[8][ORIG];
    __shared__ float hs[8][AFL];
    __shared__ float red[16];
    int tid = threadIdx.x;
    int g = tid >> 6, c = tid & 63;
    int n = blockIdx.x * 8 + g;
    for (int i = tid; i < ORIG * AFL; i += 512) Ws[i] = W[i];
    for (int i = tid; i < AFL * AFL; i += 512) ppWs[i] = ppW[i];
    for (int i = tid; i < 8 * ORIG; i += 512) {
        int gg = i / ORIG, k = i - gg * ORIG;
        xs[gg][k] = x[(blockIdx.x * 8 + gg) * ORIG + k] * att[k];
    }
    __syncthreads();
    float acc = b[c];
#pragma unroll 4
    for (int k = 0; k < ORIG; k++) acc = fmaf(xs[g][k], Ws[k * AFL + c], acc);
    g_h[n * AFL + c] = acc;
    hs[g][c] = acc;
    __syncthreads();
    float p = ppb[c];
#pragma unroll 8
    for (int k = 0; k < AFL; k++) p = fmaf(hs[g][k], ppWs[k * AFL + c], p);
    int wid = tid >> 5;
    float m = p;
#pragma unroll
    for (int o = 16; o; o >>= 1) m = fmaxf(m, __shfl_xor_sync(0xffffffffu, m, o));
    if ((tid & 31) == 0) red[wid] = m;
    __syncthreads();
    m = fmaxf(red[g * 2], red[g * 2 + 1]);
    float ex = expf(p - m);
    float s = ex;
#pragma unroll
    for (int o = 16; o; o >>= 1) s += __shfl_xor_sync(0xffffffffu, s, o);
    __syncthreads();
    if ((tid & 31) == 0) red[wid] = s;
    __syncthreads();
    s = red[g * 2] + red[g * 2 + 1];
    int numAtom = N_NODES / bs[0];
    atomicAdd(&out[(n / numAtom) * AFL + c], ex / s);
}

// ---------------- per-layer: M = lut @ fcW[128:192] ----------------
__global__ void __launch_bounds__(FCO) k_prepM(
    const float* __restrict__ lut, const float* __restrict__ fcW)
{
    int j = blockIdx.x, c = threadIdx.x;
    float acc = 0.f;
#pragma unroll 4
    for (int m = 0; m < AFL; m++)
        acc = fmaf(lut[j * AFL + m], fcW[(2 * AFL + m) * FCO + c], acc);
    g_M[j * FCO + c] = acc;
}

// ---------------- per-layer lookup table ----------------
__global__ void __launch_bounds__(FCO) k_table(
    const float* __restrict__ w1, const float* __restrict__ b1,
    const float* __restrict__ w2, const float* __restrict__ b2,
    const float* __restrict__ alpha, const float* __restrict__ fcb)
{
    __shared__ float v2[BINS];
    __shared__ float p[BINS];
    __shared__ float redA[4];
    __shared__ float redB[4];
    int tid = threadIdx.x;
    float a = (float)blockIdx.x / (float)(TBL - 1);
    if (tid < BINS) {
        float v = fmaf(a, w1[tid], b1[tid]);
        v2[tid] = v > 0.f ? v : 0.01f * v;
    }
    __syncthreads();
    float v3 = -3.0e38f;
    if (tid < BINS) {
        float acc = fmaf(alpha[0], v2[tid], b2[tid]);
#pragma unroll 4
        for (int k = 0; k < BINS; k++) acc = fmaf(v2[k], w2[k * BINS + tid], acc);
        v3 = acc;
    }
    float m = v3;
#pragma unroll
    for (int o = 16; o; o >>= 1) m = fmaxf(m, __shfl_xor_sync(0xffffffffu, m, o));
    if ((tid & 31) == 0) redA[tid >> 5] = m;
    __syncthreads();
    m = fmaxf(fmaxf(redA[0], redA[1]), fmaxf(redA[2], redA[3]));
    float ex = (tid < BINS) ? expf(v3 - m) : 0.f;
    float s = ex;
#pragma unroll
    for (int o = 16; o; o >>= 1) s += __shfl_xor_sync(0xffffffffu, s, o);
    if ((tid & 31) == 0) redB[tid >> 5] = s;
    __syncthreads();
    s = (redB[0] + redB[1]) + (redB[2] + redB[3]);
    float inv = 1.f / s;
    if (tid < BINS) p[tid] = ex * inv;
    __syncthreads();
    float acc = fcb[tid];
#pragma unroll 4
    for (int j = 0; j < BINS; j++) acc = fmaf(p[j], g_M[j * FCO + tid], acc);
    g_T[blockIdx.x * FCO + tid] = acc;
}

// ---------------- node projections: both halves, 32 rows/block ----------------
__global__ void __launch_bounds__(256) k_proj(const float* __restrict__ fcW)
{
    __shared__ float Wsh[32 * 256];          // 32 KB (k-chunk of both halves)
    __shared__ float hsh[AFL][PROJ_ROWS];    // 8 KB
    int c = threadIdx.x;                     // 256: col in [Zd(128) | Zs(128)]
    int half = c >> 7;                       // 0 -> Zd, 1 -> Zs
    int cc = c & 127;
    int r0 = blockIdx.x * PROJ_ROWS;
    for (int i = c; i < PROJ_ROWS * AFL; i += 256) {
        int r = i >> 6, k = i & 63;
        hsh[k][r] = g_h[(r0 + r) * AFL + k];
    }
    float acc[PROJ_ROWS];
#pragma unroll
    for (int r = 0; r < PROJ_ROWS; r++) acc[r] = 0.f;

    for (int kc = 0; kc < 2; kc++) {
        __syncthreads();
        // load 32 k-rows of both weight halves: Wsh[k'][c]
        for (int i = c; i < 32 * 256; i += 256) {
            int kk = i >> 8;
            int col = i & 255;
            int h2 = col >> 7, c2 = col & 127;
            Wsh[i] = fcW[(h2 * AFL + kc * 32 + kk) * FCO + c2];
        }
        __syncthreads();
#pragma unroll 4
        for (int kk = 0; kk < 32; kk++) {
            float w = Wsh[kk * 256 + c];
            const float4* hv = reinterpret_cast<const float4*>(&hsh[kc * 32 + kk][0]);
#pragma unroll
            for (int q = 0; q < PROJ_ROWS / 4; q++) {
                float4 h4 = hv[q];
                acc[q * 4 + 0] = fmaf(h4.x, w, acc[q * 4 + 0]);
                acc[q * 4 + 1] = fmaf(h4.y, w, acc[q * 4 + 1]);
                acc[q * 4 + 2] = fmaf(h4.z, w, acc[q * 4 + 2]);
                acc[q * 4 + 3] = fmaf(h4.w, w, acc[q * 4 + 3]);
            }
        }
    }
    float* dst = half ? g_Zs : g_Zd;
#pragma unroll
    for (int r = 0; r < PROJ_ROWS; r++) dst[(size_t)(r0 + r) * FCO + cc] = acc[r];
}

// ---------------- edge z helper ----------------
__device__ __forceinline__ float4 zval(const float4& zd, const float4& zs,
                                       float a, int lane)
{
    float pos = fminf(fmaxf(a * (float)(TBL - 1), 0.f), (float)(TBL - 1));
    int t0 = min((int)pos, TBL - 2);
    float w = pos - (float)t0;
    float4 T0 = __ldg(reinterpret_cast<const float4*>(&g_T[t0 * FCO]) + lane);
    float4 T1 = __ldg(reinterpret_cast<const float4*>(&g_T[(t0 + 1) * FCO]) + lane);
    float4 z;
    z.x = zd.x + zs.x + fmaf(w, T1.x - T0.x, T0.x);
    z.y = zd.y + zs.y + fmaf(w, T1.y - T0.y, T0.y);
    z.z = zd.z + zs.z + fmaf(w, T1.z - T0.z, T0.z);
    z.w = zd.w + zs.w + fmaf(w, T1.w - T0.w, T0.w);
    return z;
}

__device__ __forceinline__ void acc_stats(const float4& z, float4& ps, float4& pq) {
    ps.x += z.x; ps.y += z.y; ps.z += z.z; ps.w += z.w;
    pq.x = fmaf(z.x, z.x, pq.x); pq.y = fmaf(z.y, z.y, pq.y);
    pq.z = fmaf(z.z, z.z, pq.z); pq.w = fmaf(z.w, z.w, pq.w);
}

// ---------------- pass C: BN1 stats (4-wide pipelined gathers) ----------------
__global__ void __launch_bounds__(256) k_edgeC()
{
    __shared__ float sred[8 * 256];
    int warp = threadIdx.x >> 5, lane = threadIdx.x & 31;
    int gw = blockIdx.x * 8 + warp;
    int nw = gridDim.x * 8;
    float4 ps = {0, 0, 0, 0}, pq = {0, 0, 0, 0};
    for (int n = gw; n < N_NODES; n += nw) {
        int beg = g_segstart[n], end = g_segstart[n + 1];
        if (beg == end) continue;
        float4 zd = __ldg(reinterpret_cast<const float4*>(&g_Zd[(size_t)n * FCO]) + lane);
        for (int base = beg; base < end; base += 32) {
            int e = base + lane;
            int sv = 0; float av = 0.f;
            if (e < end) { sv = g_psrc[e]; av = g_pattr[e]; }
            int cnt = min(32, end - base);
            int j = 0;
            for (; j + 4 <= cnt; j += 4) {
                int s0 = __shfl_sync(0xffffffffu, sv, j + 0);
                int s1 = __shfl_sync(0xffffffffu, sv, j + 1);
                int s2 = __shfl_sync(0xffffffffu, sv, j + 2);
                int s3 = __shfl_sync(0xffffffffu, sv, j + 3);
                float a0 = __shfl_sync(0xffffffffu, av, j + 0);
                float a1 = __shfl_sync(0xffffffffu, av, j + 1);
                float a2 = __shfl_sync(0xffffffffu, av, j + 2);
                float a3 = __shfl_sync(0xffffffffu, av, j + 3);
                float4 zs0 = __ldg(reinterpret_cast<const float4*>(&g_Zs[(size_t)s0 * FCO]) + lane);
                float4 zs1 = __ldg(reinterpret_cast<const float4*>(&g_Zs[(size_t)s1 * FCO]) + lane);
                float4 zs2 = __ldg(reinterpret_cast<const float4*>(&g_Zs[(size_t)s2 * FCO]) + lane);
                float4 zs3 = __ldg(reinterpret_cast<const float4*>(&g_Zs[(size_t)s3 * FCO]) + lane);
                acc_stats(zval(zd, zs0, a0, lane), ps, pq);
                acc_stats(zval(zd, zs1, a1, lane), ps, pq);
                acc_stats(zval(zd, zs2, a2, lane), ps, pq);
                acc_stats(zval(zd, zs3, a3, lane), ps, pq);
            }
            for (; j < cnt; j++) {
                int s0 = __shfl_sync(0xffffffffu, sv, j);
                float a0 = __shfl_sync(0xffffffffu, av, j);
                float4 zs0 = __ldg(reinterpret_cast<const float4*>(&g_Zs[(size_t)s0 * FCO]) + lane);
                acc_stats(zval(zd, zs0, a0, lane), ps, pq);
            }
        }
    }
    int b = warp * 256 + 4 * lane;
    sred[b + 0] = ps.x; sred[b + 1] = ps.y; sred[b + 2] = ps.z; sred[b + 3] = ps.w;
    sred[b + 128] = pq.x; sred[b + 129] = pq.y; sred[b + 130] = pq.z; sred[b + 131] = pq.w;
    __syncthreads();
    int tid = threadIdx.x;
    float v = 0.f;
#pragma unroll
    for (int w = 0; w < 8; w++) v += sred[w * 256 + tid];
    g_part1[blockIdx.x * 256 + tid] = v;
}

__global__ void __launch_bounds__(256) k_red1(
    const float* __restrict__ g1, const float* __restrict__ b1)
{
    __shared__ float sh[256];
    int tid = threadIdx.x;
    float s = 0.f;
#pragma unroll 4
    for (int b = 0; b < EGRID; b++) s += g_part1[b * 256 + tid];
    sh[tid] = s;
    __syncthreads();
    if (tid < FCO) {
        const float invE = 1.f / (float)N_EDGES;
        float mu = sh[tid] * invE;
        float var = sh[128 + tid] * invE - mu * mu;
        float sc = rsqrtf(var + EPS_BN) * g1[tid];
        g_bn1sc[tid] = sc;
        g_bn1sh[tid] = fmaf(-mu, sc, b1[tid]);
    }
}

// ---------------- pass D: message + segment sum + BN2 stats ----------------
__device__ __forceinline__ void msg_acc(const float4& z, const float4& sc4,
                                        const float4& sh4, int lane, float4& acc)
{
    float4 r;
    r.x = fmaxf(fmaf(z.x, sc4.x, sh4.x), 0.f);
    r.y = fmaxf(fmaf(z.y, sc4.y, sh4.y), 0.f);
    r.z = fmaxf(fmaf(z.z, sc4.z, sh4.z), 0.f);
    r.w = fmaxf(fmaf(z.w, sc4.w, sh4.w), 0.f);
    float cx = __shfl_down_sync(0xffffffffu, r.x, 16);
    float cy = __shfl_down_sync(0xffffffffu, r.y, 16);
    float cz = __shfl_down_sync(0xffffffffu, r.z, 16);
    float cw = __shfl_down_sync(0xffffffffu, r.w, 16);
    if (lane < 16) {
        acc.x = fmaf(r.x, cx, acc.x);
        acc.y = fmaf(r.y, cy, acc.y);
        acc.z = fmaf(r.z, cz, acc.z);
        acc.w = fmaf(r.w, cw, acc.w);
    }
}

__global__ void __launch_bounds__(256) k_edgeD()
{
    __shared__ float sred[8 * 128];
    int warp = threadIdx.x >> 5, lane = threadIdx.x & 31;
    int gw = blockIdx.x * 8 + warp;
    int nw = gridDim.x * 8;
    float4 sc4 = reinterpret_cast<const float4*>(g_bn1sc)[lane];
    float4 sh4 = reinterpret_cast<const float4*>(g_bn1sh)[lane];
    float4 ps = {0, 0, 0, 0}, pq = {0, 0, 0, 0};
    for (int n = gw; n < N_NODES; n += nw) {
        int beg = g_segstart[n], end = g_segstart[n + 1];
        float4 acc = {0, 0, 0, 0};
        if (beg < end) {
            float4 zd = __ldg(reinterpret_cast<const float4*>(&g_Zd[(size_t)n * FCO]) + lane);
            for (int base = beg; base < end; base += 32) {
                int e = base + lane;
                int sv = 0; float av = 0.f;
                if (e < end) { sv = g_psrc[e]; av = g_pattr[e]; }
                int cnt = min(32, end - base);
                int j = 0;
                for (; j + 4 <= cnt; j += 4) {
                    int s0 = __shfl_sync(0xffffffffu, sv, j + 0);
                    int s1 = __shfl_sync(0xffffffffu, sv, j + 1);
                    int s2 = __shfl_sync(0xffffffffu, sv, j + 2);
                    int s3 = __shfl_sync(0xffffffffu, sv, j + 3);
                    float a0 = __shfl_sync(0xffffffffu, av, j + 0);
                    float a1 = __shfl_sync(0xffffffffu, av, j + 1);
                    float a2 = __shfl_sync(0xffffffffu, av, j + 2);
                    float a3 = __shfl_sync(0xffffffffu, av, j + 3);
                    float4 zs0 = __ldg(reinterpret_cast<const float4*>(&g_Zs[(size_t)s0 * FCO]) + lane);
                    float4 zs1 = __ldg(reinterpret_cast<const float4*>(&g_Zs[(size_t)s1 * FCO]) + lane);
                    float4 zs2 = __ldg(reinterpret_cast<const float4*>(&g_Zs[(size_t)s2 * FCO]) + lane);
                    float4 zs3 = __ldg(reinterpret_cast<const float4*>(&g_Zs[(size_t)s3 * FCO]) + lane);
                    msg_acc(zval(zd, zs0, a0, lane), sc4, sh4, lane, acc);
                    msg_acc(zval(zd, zs1, a1, lane), sc4, sh4, lane, acc);
                    msg_acc(zval(zd, zs2, a2, lane), sc4, sh4, lane, acc);
                    msg_acc(zval(zd, zs3, a3, lane), sc4, sh4, lane, acc);
                }
                for (; j < cnt; j++) {
                    int s0 = __shfl_sync(0xffffffffu, sv, j);
                    float a0 = __shfl_sync(0xffffffffu, av, j);
                    float4 zs0 = __ldg(reinterpret_cast<const float4*>(&g_Zs[(size_t)s0 * FCO]) + lane);
                    msg_acc(zval(zd, zs0, a0, lane), sc4, sh4, lane, acc);
                }
            }
        }
        if (lane < 16) {
            reinterpret_cast<float4*>(&g_aggr[(size_t)n * AFL])[lane] = acc;
            ps.x += acc.x; ps.y += acc.y; ps.z += acc.z; ps.w += acc.w;
            pq.x = fmaf(acc.x, acc.x, pq.x); pq.y = fmaf(acc.y, acc.y, pq.y);
            pq.z = fmaf(acc.z, acc.z, pq.z); pq.w = fmaf(acc.w, acc.w, pq.w);
        }
    }
    if (lane < 16) {
        int b = warp * 128 + 4 * lane;
        sred[b + 0] = ps.x; sred[b + 1] = ps.y; sred[b + 2] = ps.z; sred[b + 3] = ps.w;
        sred[b + 64] = pq.x; sred[b + 65] = pq.y; sred[b + 66] = pq.z; sred[b + 67] = pq.w;
    }
    __syncthreads();
    int tid = threadIdx.x;
    if (tid < 128) {
        float v = 0.f;
#pragma unroll
        for (int w = 0; w < 8; w++) v += sred[w * 128 + tid];
        g_part2[blockIdx.x * 128 + tid] = v;
    }
}

__global__ void __launch_bounds__(128) k_red2(
    const float* __restrict__ g2, const float* __restrict__ b2)
{
    __shared__ float sh[128];
    int tid = threadIdx.x;
    float s = 0.f;
#pragma unroll 4
    for (int b = 0; b < DGRID; b++) s += g_part2[b * 128 + tid];
    sh[tid] = s;
    __syncthreads();
    if (tid < AFL) {
        const float invN = 1.f / (float)N_NODES;
        float mu = sh[tid] * invN;
        float var = sh[64 + tid] * invN - mu * mu;
        float sc = rsqrtf(var + EPS_BN) * g2[tid];
        g_bn2sc[tid] = sc;
        g_bn2sh[tid] = fmaf(-mu, sc, b2[tid]);
    }
}

// ---------------- update + pooling (8 nodes/block) ----------------
__global__ void __launch_bounds__(512) k_update_pool(
    const float* __restrict__ ppW, const float* __restrict__ ppb,
    float* __restrict__ out, const int* __restrict__ bs)
{
    __shared__ float ppWs[AFL * AFL];
    __shared__ float hs[8][AFL];
    __shared__ float red[16];
    int tid = threadIdx.x;
    int g = tid >> 6, c = tid & 63;
    int n = blockIdx.x * 8 + g;
    for (int i = tid; i < AFL * AFL; i += 512) ppWs[i] = ppW[i];
    float up = fmaxf(g_h[n * AFL + c] +
                     fmaf(g_aggr[n * AFL + c], g_bn2sc[c], g_bn2sh[c]), 0.f);
    g_h[n * AFL + c] = up;
    hs[g][c] = up;
    __syncthreads();
    float p = ppb[c];
#pragma unroll 8
    for (int k = 0; k < AFL; k++) p = fmaf(hs[g][k], ppWs[k * AFL + c], p);
    int wid = tid >> 5;
    float m = p;
#pragma unroll
    for (int o = 16; o; o >>= 1) m = fmaxf(m, __shfl_xor_sync(0xffffffffu, m, o));
    if ((tid & 31) == 0) red[wid] = m;
    __syncthreads();
    m = fmaxf(red[g * 2], red[g * 2 + 1]);
    float ex = expf(p - m);
    float s = ex;
#pragma unroll
    for (int o = 16; o; o >>= 1) s += __shfl_xor_sync(0xffffffffu, s, o);
    __syncthreads();
    if ((tid & 31) == 0) red[wid] = s;
    __syncthreads();
    s = red[g * 2] + red[g * 2 + 1];
    int numAtom = N_NODES / bs[0];
    atomicAdd(&out[(n / numAtom) * AFL + c], ex / s);
}

// ---------------- launch ----------------
extern "C" void kernel_launch(void* const* d_in, const int* in_sizes, int n_in,
                              void* d_out, int out_size)
{
    const float* x     = (const float*)d_in[0];
    const int*   ei    = (const int*)  d_in[1];
    const float* ea    = (const float*)d_in[2];
    const int*   bs    = (const int*)  d_in[3];
    const float* att   = (const float*)d_in[4];
    const float* embW  = (const float*)d_in[5];
    const float* embb  = (const float*)d_in[6];
    const float* adw1  = (const float*)d_in[7];
    const float* adb1  = (const float*)d_in[8];
    const float* adw2  = (const float*)d_in[9];
    const float* adb2  = (const float*)d_in[10];
    const float* adal  = (const float*)d_in[11];
    const float* adlut = (const float*)d_in[12];
    const float* fcW   = (const float*)d_in[13];
    const float* fcb   = (const float*)d_in[14];
    const float* bn1g  = (const float*)d_in[15];
    const float* bn1b  = (const float*)d_in[16];
    const float* bn2g  = (const float*)d_in[17];
    const float* bn2b  = (const float*)d_in[18];
    const float* ppW   = (const float*)d_in[19];
    const float* ppb   = (const float*)d_in[20];
    float* out = (float*)d_out;

    // 1: zero out + cnt
    k_zero<<<64, 256>>>(out, out_size);
    // 2: embedding + first pooling
    k_embed_pool<<<N_NODES / 8, 512>>>(x, att, embW, embb, ppW, ppb, out, bs);
    // 3: layer-0 M
    k_prepM<<<BINS, FCO>>>(adlut, fcW);
    // 4: layer-0 projections  (target for the profiler slot)
    k_proj<<<N_NODES / PROJ_ROWS, 256>>>(fcW);
    // 5: layer-0 table
    k_table<<<TBL, FCO>>>(adw1, adb1, adw2, adb2, adal, fcb);
    // 6-8: edge sort (reused by all layers)
    k_hist<<<N_EDGES / 1024, 1024>>>(ei);
    k_scan<<<1, 1024>>>();
    k_scatter<<<N_EDGES / 1024, 1024>>>(ei, ea);

    for (int l = 0; l < NCONV; l++) {
        if (l > 0) {
            k_prepM<<<BINS, FCO>>>(adlut + l * BINS * AFL, fcW + l * (3 * AFL) * FCO);
            k_table<<<TBL, FCO>>>(adw1 + l * BINS, adb1 + l * BINS,
                                  adw2 + l * BINS * BINS, adb2 + l * BINS,
                                  adal + l, fcb + l * FCO);
            k_proj<<<N_NODES / PROJ_ROWS, 256>>>(fcW + l * (3 * AFL) * FCO);
        }
        k_edgeC<<<EGRID, 256>>>();
        k_red1<<<1, 256>>>(bn1g + l * FCO, bn1b + l * FCO);
        k_edgeD<<<DGRID, 256>>>();
        k_red2<<<1, 128>>>(bn2g + l * AFL, bn2b + l * AFL);
        k_update_pool<<<N_NODES / 8, 512>>>(ppW, ppb, out, bs);
    }
}

// round 4
// speedup vs baseline: 1.6601x; 1.3679x over previous
#include <cuda_runtime.h>
#include <cuda_bf16.h>
#include <cstdint>

#define N_NODES 51200
#define N_EDGES 614400
#define ORIG    92
#define AFL     64
#define BINS    100
#define NCONV   3
#define TBL     128
#define FCO     128      // 2*AFL
#define EPS_BN  1e-5f
#define EGRID   512
#define DGRID   512
#define PROJ_ROWS 64
#define HPAD    68       // row stride (words) for transposed h tile; 272B = 16B-aligned

// ---------------- device scratch (static, no allocations) ----------------
__device__ float g_h[N_NODES * AFL];
__device__ float g_Zd[N_NODES * FCO];
__device__ float g_Zs[N_NODES * FCO];
__device__ float g_T[TBL * FCO];              // 64 KB lookup table
__device__ float g_aggr[N_NODES * AFL];
__device__ float g_part1[EGRID * 256];
__device__ float g_part2[DGRID * 128];
__device__ float g_bn1sc[FCO], g_bn1sh[FCO];
__device__ float g_bn2sc[AFL], g_bn2sh[AFL];
__device__ int   g_cnt[N_NODES];
__device__ int   g_segstart[N_NODES + 1];
__device__ int   g_off[N_NODES];
__device__ int   g_psrc[N_EDGES];
__device__ float g_pattr[N_EDGES];

// ---------------- zero out + cnt ----------------
__global__ void k_zero(float* __restrict__ out, int n) {
    int i = blockIdx.x * blockDim.x + threadIdx.x;
    int stride = gridDim.x * blockDim.x;
    for (int j = i; j < n; j += stride) out[j] = 0.f;
    for (int j = i; j < N_NODES; j += stride) g_cnt[j] = 0;
}

// ---------------- embedding + initial pooling (8 nodes/block) ----------------
__global__ void __launch_bounds__(512) k_embed_pool(
    const float* __restrict__ x, const float* __restrict__ att,
    const float* __restrict__ W, const float* __restrict__ b,
    const float* __restrict__ ppW, const float* __restrict__ ppb,
    float* __restrict__ out, const int* __restrict__ bs)
{
    __shared__ float Ws[ORIG * AFL];
    __shared__ float ppWs[AFL * AFL];
    __shared__ float xs[8][ORIG];
    __shared__ float hs[8][AFL];
    __shared__ float red[16];
    int tid = threadIdx.x;
    int g = tid >> 6, c = tid & 63;
    int n = blockIdx.x * 8 + g;
    for (int i = tid; i < ORIG * AFL; i += 512) Ws[i] = W[i];
    for (int i = tid; i < AFL * AFL; i += 512) ppWs[i] = ppW[i];
    for (int i = tid; i < 8 * ORIG; i += 512) {
        int gg = i / ORIG, k = i - gg * ORIG;
        xs[gg][k] = x[(blockIdx.x * 8 + gg) * ORIG + k] * att[k];
    }
    __syncthreads();
    float acc = b[c];
#pragma unroll 4
    for (int k = 0; k < ORIG; k++) acc = fmaf(xs[g][k], Ws[k * AFL + c], acc);
    g_h[n * AFL + c] = acc;
    hs[g][c] = acc;
    __syncthreads();
    float p = ppb[c];
#pragma unroll 8
    for (int k = 0; k < AFL; k++) p = fmaf(hs[g][k], ppWs[k * AFL + c], p);
    int wid = tid >> 5;
    float m = p;
#pragma unroll
    for (int o = 16; o; o >>= 1) m = fmaxf(m, __shfl_xor_sync(0xffffffffu, m, o));
    if ((tid & 31) == 0) red[wid] = m;
    __syncthreads();
    m = fmaxf(red[g * 2], red[g * 2 + 1]);
    float ex = expf(p - m);
    float s = ex;
#pragma unroll
    for (int o = 16; o; o >>= 1) s += __shfl_xor_sync(0xffffffffu, s, o);
    __syncthreads();
    if ((tid & 31) == 0) red[wid] = s;
    __syncthreads();
    s = red[g * 2] + red[g * 2 + 1];
    int numAtom = N_NODES / bs[0];
    atomicAdd(&out[(n / numAtom) * AFL + c], ex / s);
}

// ---------------- fused table: T[t] = softmax(v3(a_t)) @ lut @ fcW[128:192] + fcb ----
__global__ void __launch_bounds__(FCO) k_table(
    const float* __restrict__ w1, const float* __restrict__ b1,
    const float* __restrict__ w2, const float* __restrict__ b2,
    const float* __restrict__ alpha, const float* __restrict__ lut,
    const float* __restrict__ fcW, const float* __restrict__ fcb)
{
    __shared__ float v2[BINS];
    __shared__ float p[BINS];
    __shared__ float q[AFL];
    __shared__ float redA[4];
    __shared__ float redB[4];
    int tid = threadIdx.x;
    float a = (float)blockIdx.x / (float)(TBL - 1);
    if (tid < BINS) {
        float v = fmaf(a, w1[tid], b1[tid]);
        v2[tid] = v > 0.f ? v : 0.01f * v;
    }
    __syncthreads();
    float v3 = -3.0e38f;
    if (tid < BINS) {
        float acc = fmaf(alpha[0], v2[tid], b2[tid]);
#pragma unroll 4
        for (int k = 0; k < BINS; k++) acc = fmaf(v2[k], w2[k * BINS + tid], acc);
        v3 = acc;
    }
    float m = v3;
#pragma unroll
    for (int o = 16; o; o >>= 1) m = fmaxf(m, __shfl_xor_sync(0xffffffffu, m, o));
    if ((tid & 31) == 0) redA[tid >> 5] = m;
    __syncthreads();
    m = fmaxf(fmaxf(redA[0], redA[1]), fmaxf(redA[2], redA[3]));
    float ex = (tid < BINS) ? expf(v3 - m) : 0.f;
    float s = ex;
#pragma unroll
    for (int o = 16; o; o >>= 1) s += __shfl_xor_sync(0xffffffffu, s, o);
    if ((tid & 31) == 0) redB[tid >> 5] = s;
    __syncthreads();
    s = (redB[0] + redB[1]) + (redB[2] + redB[3]);
    float inv = 1.f / s;
    if (tid < BINS) p[tid] = ex * inv;
    __syncthreads();
    // q[m] = p @ lut[:, m]
    if (tid < AFL) {
        float acc = 0.f;
#pragma unroll 4
        for (int j = 0; j < BINS; j++) acc = fmaf(p[j], lut[j * AFL + tid], acc);
        q[tid] = acc;
    }
    __syncthreads();
    // T[c] = fcb[c] + q @ fcW[128:192, c]
    float acc = fcb[tid];
#pragma unroll 4
    for (int mm = 0; mm < AFL; mm++)
        acc = fmaf(q[mm], fcW[(2 * AFL + mm) * FCO + tid], acc);
    g_T[blockIdx.x * FCO + tid] = acc;
}

// ---------------- node projections: register-tiled 64x256 blocks ----------------
__global__ void __launch_bounds__(256) k_proj(const float* __restrict__ fcW)
{
    __shared__ float Wsh[16 * 256];           // 16 KB: one k-chunk, both halves
    __shared__ float hsh[AFL * HPAD];         // 17.4 KB: transposed h tile
    int tid = threadIdx.x;
    int tx = tid & 63;                        // col4 group: cols 4*tx..4*tx+3
    int ty = tid >> 6;                        // 0..3: rows ty*16..+16
    int r0 = blockIdx.x * PROJ_ROWS;
    int col = 4 * tx;

    // load + transpose h tile: hsh[k*HPAD + r] = h[r0+r][k]
    for (int i = tid; i < PROJ_ROWS * AFL; i += 256) {
        int r = i >> 6, k = i & 63;
        hsh[k * HPAD + r] = g_h[(size_t)(r0 + r) * AFL + k];
    }

    float4 acc[16];
#pragma unroll
    for (int r = 0; r < 16; r++) acc[r] = make_float4(0.f, 0.f, 0.f, 0.f);

    for (int kc = 0; kc < 4; kc++) {
        __syncthreads();
        // load 16 k-rows of both weight halves interleaved by col
        for (int i = tid; i < 16 * 256; i += 256) {
            int kk = i >> 8;
            int cl = i & 255;
            int h2 = cl >> 7, c2 = cl & 127;
            Wsh[i] = fcW[(size_t)(h2 * AFL + kc * 16 + kk) * FCO + c2];
        }
        __syncthreads();
#pragma unroll
        for (int kk = 0; kk < 16; kk++) {
            float4 w4 = *reinterpret_cast<const float4*>(&Wsh[kk * 256 + col]);
            const float* hrow = &hsh[(kc * 16 + kk) * HPAD + ty * 16];
#pragma unroll
            for (int i = 0; i < 4; i++) {
                float4 h4 = *reinterpret_cast<const float4*>(hrow + 4 * i);
                acc[4 * i + 0].x = fmaf(h4.x, w4.x, acc[4 * i + 0].x);
                acc[4 * i + 0].y = fmaf(h4.x, w4.y, acc[4 * i + 0].y);
                acc[4 * i + 0].z = fmaf(h4.x, w4.z, acc[4 * i + 0].z);
                acc[4 * i + 0].w = fmaf(h4.x, w4.w, acc[4 * i + 0].w);
                acc[4 * i + 1].x = fmaf(h4.y, w4.x, acc[4 * i + 1].x);
                acc[4 * i + 1].y = fmaf(h4.y, w4.y, acc[4 * i + 1].y);
                acc[4 * i + 1].z = fmaf(h4.y, w4.z, acc[4 * i + 1].z);
                acc[4 * i + 1].w = fmaf(h4.y, w4.w, acc[4 * i + 1].w);
                acc[4 * i + 2].x = fmaf(h4.z, w4.x, acc[4 * i + 2].x);
                acc[4 * i + 2].y = fmaf(h4.z, w4.y, acc[4 * i + 2].y);
                acc[4 * i + 2].z = fmaf(h4.z, w4.z, acc[4 * i + 2].z);
                acc[4 * i + 2].w = fmaf(h4.z, w4.w, acc[4 * i + 2].w);
                acc[4 * i + 3].x = fmaf(h4.w, w4.x, acc[4 * i + 3].x);
                acc[4 * i + 3].y = fmaf(h4.w, w4.y, acc[4 * i + 3].y);
                acc[4 * i + 3].z = fmaf(h4.w, w4.z, acc[4 * i + 3].z);
                acc[4 * i + 3].w = fmaf(h4.w, w4.w, acc[4 * i + 3].w);
            }
        }
    }
    int half = col >> 7;
    int cc = col & 127;
    float* dst = half ? g_Zs : g_Zd;
#pragma unroll
    for (int r = 0; r < 16; r++)
        *reinterpret_cast<float4*>(&dst[(size_t)(r0 + ty * 16 + r) * FCO + cc]) = acc[r];
}

// ---------------- edge sort ----------------
__global__ void __launch_bounds__(1024) k_hist(const int* __restrict__ ei) {
    int e = blockIdx.x * blockDim.x + threadIdx.x;
    if (e < N_EDGES) atomicAdd(&g_cnt[ei[N_EDGES + e]], 1);
}

__global__ void __launch_bounds__(1024) k_scan() {
    __shared__ int wsum[32];
    __shared__ int carry;
    int tid = threadIdx.x;
    int lane = tid & 31, wid = tid >> 5;
    if (tid == 0) carry = 0;
    __syncthreads();
    for (int base = 0; base < N_NODES; base += 1024) {
        int v = g_cnt[base + tid];
        int x = v;
#pragma unroll
        for (int o = 1; o < 32; o <<= 1) {
            int t = __shfl_up_sync(0xffffffffu, x, o);
            if (lane >= o) x += t;
        }
        if (lane == 31) wsum[wid] = x;
        __syncthreads();
        if (wid == 0) {
            int sv = wsum[lane];
#pragma unroll
            for (int o = 1; o < 32; o <<= 1) {
                int t = __shfl_up_sync(0xffffffffu, sv, o);
                if (lane >= o) sv += t;
            }
            wsum[lane] = sv;
        }
        __syncthreads();
        int woff = (wid > 0) ? wsum[wid - 1] : 0;
        int ex = carry + woff + x - v;
        g_segstart[base + tid] = ex;
        g_off[base + tid] = ex;
        __syncthreads();
        if (tid == 0) carry += wsum[31];
        __syncthreads();
    }
    if (tid == 0) g_segstart[N_NODES] = N_EDGES;
}

__global__ void __launch_bounds__(1024) k_scatter(const int* __restrict__ ei,
                                                  const float* __restrict__ ea) {
    int e = blockIdx.x * blockDim.x + threadIdx.x;
    if (e < N_EDGES) {
        int dst = ei[N_EDGES + e];
        int pos = atomicAdd(&g_off[dst], 1);
        g_psrc[pos] = ei[e];
        g_pattr[pos] = ea[e];
    }
}

// ---------------- edge z helper ----------------
__device__ __forceinline__ float4 zval(const float4& zd, const float4& zs,
                                       float a, int lane)
{
    float pos = fminf(fmaxf(a * (float)(TBL - 1), 0.f), (float)(TBL - 1));
    int t0 = min((int)pos, TBL - 2);
    float w = pos - (float)t0;
    float4 T0 = __ldg(reinterpret_cast<const float4*>(&g_T[t0 * FCO]) + lane);
    float4 T1 = __ldg(reinterpret_cast<const float4*>(&g_T[(t0 + 1) * FCO]) + lane);
    float4 z;
    z.x = zd.x + zs.x + fmaf(w, T1.x - T0.x, T0.x);
    z.y = zd.y + zs.y + fmaf(w, T1.y - T0.y, T0.y);
    z.z = zd.z + zs.z + fmaf(w, T1.z - T0.z, T0.z);
    z.w = zd.w + zs.w + fmaf(w, T1.w - T0.w, T0.w);
    return z;
}

__device__ __forceinline__ void acc_stats(const float4& z, float4& ps, float4& pq) {
    ps.x += z.x; ps.y += z.y; ps.z += z.z; ps.w += z.w;
    pq.x = fmaf(z.x, z.x, pq.x); pq.y = fmaf(z.y, z.y, pq.y);
    pq.z = fmaf(z.z, z.z, pq.z); pq.w = fmaf(z.w, z.w, pq.w);
}

// ---------------- pass C: BN1 stats ----------------
__global__ void __launch_bounds__(256) k_edgeC()
{
    __shared__ float sred[8 * 256];
    int warp = threadIdx.x >> 5, lane = threadIdx.x & 31;
    int gw = blockIdx.x * 8 + warp;
    int nw = gridDim.x * 8;
    float4 ps = {0, 0, 0, 0}, pq = {0, 0, 0, 0};
    for (int n = gw; n < N_NODES; n += nw) {
        int beg = g_segstart[n], end = g_segstart[n + 1];
        if (beg == end) continue;
        float4 zd = __ldg(reinterpret_cast<const float4*>(&g_Zd[(size_t)n * FCO]) + lane);
        for (int base = beg; base < end; base += 32) {
            int e = base + lane;
            int sv = 0; float av = 0.f;
            if (e < end) { sv = g_psrc[e]; av = g_pattr[e]; }
            int cnt = min(32, end - base);
            int j = 0;
            for (; j + 4 <= cnt; j += 4) {
                int s0 = __shfl_sync(0xffffffffu, sv, j + 0);
                int s1 = __shfl_sync(0xffffffffu, sv, j + 1);
                int s2 = __shfl_sync(0xffffffffu, sv, j + 2);
                int s3 = __shfl_sync(0xffffffffu, sv, j + 3);
                float a0 = __shfl_sync(0xffffffffu, av, j + 0);
                float a1 = __shfl_sync(0xffffffffu, av, j + 1);
                float a2 = __shfl_sync(0xffffffffu, av, j + 2);
                float a3 = __shfl_sync(0xffffffffu, av, j + 3);
                float4 zs0 = __ldg(reinterpret_cast<const float4*>(&g_Zs[(size_t)s0 * FCO]) + lane);
                float4 zs1 = __ldg(reinterpret_cast<const float4*>(&g_Zs[(size_t)s1 * FCO]) + lane);
                float4 zs2 = __ldg(reinterpret_cast<const float4*>(&g_Zs[(size_t)s2 * FCO]) + lane);
                float4 zs3 = __ldg(reinterpret_cast<const float4*>(&g_Zs[(size_t)s3 * FCO]) + lane);
                acc_stats(zval(zd, zs0, a0, lane), ps, pq);
                acc_stats(zval(zd, zs1, a1, lane), ps, pq);
                acc_stats(zval(zd, zs2, a2, lane), ps, pq);
                acc_stats(zval(zd, zs3, a3, lane), ps, pq);
            }
            for (; j < cnt; j++) {
                int s0 = __shfl_sync(0xffffffffu, sv, j);
                float a0 = __shfl_sync(0xffffffffu, av, j);
                float4 zs0 = __ldg(reinterpret_cast<const float4*>(&g_Zs[(size_t)s0 * FCO]) + lane);
                acc_stats(zval(zd, zs0, a0, lane), ps, pq);
            }
        }
    }
    int b = warp * 256 + 4 * lane;
    sred[b + 0] = ps.x; sred[b + 1] = ps.y; sred[b + 2] = ps.z; sred[b + 3] = ps.w;
    sred[b + 128] = pq.x; sred[b + 129] = pq.y; sred[b + 130] = pq.z; sred[b + 131] = pq.w;
    __syncthreads();
    int tid = threadIdx.x;
    float v = 0.f;
#pragma unroll
    for (int w = 0; w < 8; w++) v += sred[w * 256 + tid];
    g_part1[blockIdx.x * 256 + tid] = v;
}

// parallel BN1 reduce: one block per channel
__global__ void __launch_bounds__(256) k_red1(
    const float* __restrict__ g1, const float* __restrict__ b1)
{
    __shared__ float ssum[256], ssq[256];
    int c = blockIdx.x;       // 0..127
    int t = threadIdx.x;
    float s = 0.f, q = 0.f;
    for (int r = t; r < EGRID; r += 256) {
        s += g_part1[r * 256 + c];
        q += g_part1[r * 256 + 128 + c];
    }
    ssum[t] = s; ssq[t] = q;
    __syncthreads();
    for (int o = 128; o; o >>= 1) {
        if (t < o) { ssum[t] += ssum[t + o]; ssq[t] += ssq[t + o]; }
        __syncthreads();
    }
    if (t == 0) {
        const float invE = 1.f / (float)N_EDGES;
        float mu = ssum[0] * invE;
        float var = ssq[0] * invE - mu * mu;
        float sc = rsqrtf(var + EPS_BN) * g1[c];
        g_bn1sc[c] = sc;
        g_bn1sh[c] = fmaf(-mu, sc, b1[c]);
    }
}

// ---------------- pass D ----------------
__device__ __forceinline__ void msg_acc(const float4& z, const float4& sc4,
                                        const float4& sh4, int lane, float4& acc)
{
    float4 r;
    r.x = fmaxf(fmaf(z.x, sc4.x, sh4.x), 0.f);
    r.y = fmaxf(fmaf(z.y, sc4.y, sh4.y), 0.f);
    r.z = fmaxf(fmaf(z.z, sc4.z, sh4.z), 0.f);
    r.w = fmaxf(fmaf(z.w, sc4.w, sh4.w), 0.f);
    float cx = __shfl_down_sync(0xffffffffu, r.x, 16);
    float cy = __shfl_down_sync(0xffffffffu, r.y, 16);
    float cz = __shfl_down_sync(0xffffffffu, r.z, 16);
    float cw = __shfl_down_sync(0xffffffffu, r.w, 16);
    if (lane < 16) {
        acc.x = fmaf(r.x, cx, acc.x);
        acc.y = fmaf(r.y, cy, acc.y);
        acc.z = fmaf(r.z, cz, acc.z);
        acc.w = fmaf(r.w, cw, acc.w);
    }
}

__global__ void __launch_bounds__(256) k_edgeD()
{
    __shared__ float sred[8 * 128];
    int warp = threadIdx.x >> 5, lane = threadIdx.x & 31;
    int gw = blockIdx.x * 8 + warp;
    int nw = gridDim.x * 8;
    float4 sc4 = reinterpret_cast<const float4*>(g_bn1sc)[lane];
    float4 sh4 = reinterpret_cast<const float4*>(g_bn1sh)[lane];
    float4 ps = {0, 0, 0, 0}, pq = {0, 0, 0, 0};
    for (int n = gw; n < N_NODES; n += nw) {
        int beg = g_segstart[n], end = g_segstart[n + 1];
        float4 acc = {0, 0, 0, 0};
        if (beg < end) {
            float4 zd = __ldg(reinterpret_cast<const float4*>(&g_Zd[(size_t)n * FCO]) + lane);
            for (int base = beg; base < end; base += 32) {
                int e = base + lane;
                int sv = 0; float av = 0.f;
                if (e < end) { sv = g_psrc[e]; av = g_pattr[e]; }
                int cnt = min(32, end - base);
                int j = 0;
                for (; j + 4 <= cnt; j += 4) {
                    int s0 = __shfl_sync(0xffffffffu, sv, j + 0);
                    int s1 = __shfl_sync(0xffffffffu, sv, j + 1);
                    int s2 = __shfl_sync(0xffffffffu, sv, j + 2);
                    int s3 = __shfl_sync(0xffffffffu, sv, j + 3);
                    float a0 = __shfl_sync(0xffffffffu, av, j + 0);
                    float a1 = __shfl_sync(0xffffffffu, av, j + 1);
                    float a2 = __shfl_sync(0xffffffffu, av, j + 2);
                    float a3 = __shfl_sync(0xffffffffu, av, j + 3);
                    float4 zs0 = __ldg(reinterpret_cast<const float4*>(&g_Zs[(size_t)s0 * FCO]) + lane);
                    float4 zs1 = __ldg(reinterpret_cast<const float4*>(&g_Zs[(size_t)s1 * FCO]) + lane);
                    float4 zs2 = __ldg(reinterpret_cast<const float4*>(&g_Zs[(size_t)s2 * FCO]) + lane);
                    float4 zs3 = __ldg(reinterpret_cast<const float4*>(&g_Zs[(size_t)s3 * FCO]) + lane);
                    msg_acc(zval(zd, zs0, a0, lane), sc4, sh4, lane, acc);
                    msg_acc(zval(zd, zs1, a1, lane), sc4, sh4, lane, acc);
                    msg_acc(zval(zd, zs2, a2, lane), sc4, sh4, lane, acc);
                    msg_acc(zval(zd, zs3, a3, lane), sc4, sh4, lane, acc);
                }
                for (; j < cnt; j++) {
                    int s0 = __shfl_sync(0xffffffffu, sv, j);
                    float a0 = __shfl_sync(0xffffffffu, av, j);
                    float4 zs0 = __ldg(reinterpret_cast<const float4*>(&g_Zs[(size_t)s0 * FCO]) + lane);
                    msg_acc(zval(zd, zs0, a0, lane), sc4, sh4, lane, acc);
                }
            }
        }
        if (lane < 16) {
            reinterpret_cast<float4*>(&g_aggr[(size_t)n * AFL])[lane] = acc;
            ps.x += acc.x; ps.y += acc.y; ps.z += acc.z; ps.w += acc.w;
            pq.x = fmaf(acc.x, acc.x, pq.x); pq.y = fmaf(acc.y, acc.y, pq.y);
            pq.z = fmaf(acc.z, acc.z, pq.z); pq.w = fmaf(acc.w, acc.w, pq.w);
        }
    }
    if (lane < 16) {
        int b = warp * 128 + 4 * lane;
        sred[b + 0] = ps.x; sred[b + 1] = ps.y; sred[b + 2] = ps.z; sred[b + 3] = ps.w;
        sred[b + 64] = pq.x; sred[b + 65] = pq.y; sred[b + 66] = pq.z; sred[b + 67] = pq.w;
    }
    __syncthreads();
    int tid = threadIdx.x;
    if (tid < 128) {
        float v = 0.f;
#pragma unroll
        for (int w = 0; w < 8; w++) v += sred[w * 128 + tid];
        g_part2[blockIdx.x * 128 + tid] = v;
    }
}

// parallel BN2 reduce: one block per channel
__global__ void __launch_bounds__(256) k_red2(
    const float* __restrict__ g2, const float* __restrict__ b2)
{
    __shared__ float ssum[256], ssq[256];
    int c = blockIdx.x;       // 0..63
    int t = threadIdx.x;
    float s = 0.f, q = 0.f;
    for (int r = t; r < DGRID; r += 256) {
        s += g_part2[r * 128 + c];
        q += g_part2[r * 128 + 64 + c];
    }
    ssum[t] = s; ssq[t] = q;
    __syncthreads();
    for (int o = 128; o; o >>= 1) {
        if (t < o) { ssum[t] += ssum[t + o]; ssq[t] += ssq[t + o]; }
        __syncthreads();
    }
    if (t == 0) {
        const float invN = 1.f / (float)N_NODES;
        float mu = ssum[0] * invN;
        float var = ssq[0] * invN - mu * mu;
        float sc = rsqrtf(var + EPS_BN) * g2[c];
        g_bn2sc[c] = sc;
        g_bn2sh[c] = fmaf(-mu, sc, b2[c]);
    }
}

// ---------------- update + pooling (8 nodes/block) ----------------
__global__ void __launch_bounds__(512) k_update_pool(
    const float* __restrict__ ppW, const float* __restrict__ ppb,
    float* __restrict__ out, const int* __restrict__ bs)
{
    __shared__ float ppWs[AFL * AFL];
    __shared__ float hs[8][AFL];
    __shared__ float red[16];
    int tid = threadIdx.x;
    int g = tid >> 6, c = tid & 63;
    int n = blockIdx.x * 8 + g;
    for (int i = tid; i < AFL * AFL; i += 512) ppWs[i] = ppW[i];
    float up = fmaxf(g_h[n * AFL + c] +
                     fmaf(g_aggr[n * AFL + c], g_bn2sc[c], g_bn2sh[c]), 0.f);
    g_h[n * AFL + c] = up;
    hs[g][c] = up;
    __syncthreads();
    float p = ppb[c];
#pragma unroll 8
    for (int k = 0; k < AFL; k++) p = fmaf(hs[g][k], ppWs[k * AFL + c], p);
    int wid = tid >> 5;
    float m = p;
#pragma unroll
    for (int o = 16; o; o >>= 1) m = fmaxf(m, __shfl_xor_sync(0xffffffffu, m, o));
    if ((tid & 31) == 0) red[wid] = m;
    __syncthreads();
    m = fmaxf(red[g * 2], red[g * 2 + 1]);
    float ex = expf(p - m);
    float s = ex;
#pragma unroll
    for (int o = 16; o; o >>= 1) s += __shfl_xor_sync(0xffffffffu, s, o);
    __syncthreads();
    if ((tid & 31) == 0) red[wid] = s;
    __syncthreads();
    s = red[g * 2] + red[g * 2 + 1];
    int numAtom = N_NODES / bs[0];
    atomicAdd(&out[(n / numAtom) * AFL + c], ex / s);
}

// ---------------- launch ----------------
extern "C" void kernel_launch(void* const* d_in, const int* in_sizes, int n_in,
                              void* d_out, int out_size)
{
    const float* x     = (const float*)d_in[0];
    const int*   ei    = (const int*)  d_in[1];
    const float* ea    = (const float*)d_in[2];
    const int*   bs    = (const int*)  d_in[3];
    const float* att   = (const float*)d_in[4];
    const float* embW  = (const float*)d_in[5];
    const float* embb  = (const float*)d_in[6];
    const float* adw1  = (const float*)d_in[7];
    const float* adb1  = (const float*)d_in[8];
    const float* adw2  = (const float*)d_in[9];
    const float* adb2  = (const float*)d_in[10];
    const float* adal  = (const float*)d_in[11];
    const float* adlut = (const float*)d_in[12];
    const float* fcW   = (const float*)d_in[13];
    const float* fcb   = (const float*)d_in[14];
    const float* bn1g  = (const float*)d_in[15];
    const float* bn1b  = (const float*)d_in[16];
    const float* bn2g  = (const float*)d_in[17];
    const float* bn2b  = (const float*)d_in[18];
    const float* ppW   = (const float*)d_in[19];
    const float* ppb   = (const float*)d_in[20];
    float* out = (float*)d_out;

    // 1: zero out + cnt
    k_zero<<<64, 256>>>(out, out_size);
    // 2: embedding + first pooling
    k_embed_pool<<<N_NODES / 8, 512>>>(x, att, embW, embb, ppW, ppb, out, bs);
    // 3: layer-0 table (fused prepM)
    k_table<<<TBL, FCO>>>(adw1, adb1, adw2, adb2, adal, adlut, fcW, fcb);
    // 4: layer-0 projections  (profiler slot)
    k_proj<<<N_NODES / PROJ_ROWS, 256>>>(fcW);
    // 5-7: edge sort (reused by all layers)
    k_hist<<<N_EDGES / 1024, 1024>>>(ei);
    k_scan<<<1, 1024>>>();
    k_scatter<<<N_EDGES / 1024, 1024>>>(ei, ea);

    for (int l = 0; l < NCONV; l++) {
        if (l > 0) {
            k_table<<<TBL, FCO>>>(adw1 + l * BINS, adb1 + l * BINS,
                                  adw2 + l * BINS * BINS, adb2 + l * BINS,
                                  adal + l, adlut + l * BINS * AFL,
                                  fcW + l * (3 * AFL) * FCO, fcb + l * FCO);
            k_proj<<<N_NODES / PROJ_ROWS, 256>>>(fcW + l * (3 * AFL) * FCO);
        }
        k_edgeC<<<EGRID, 256>>>();
        k_red1<<<FCO, 256>>>(bn1g + l * FCO, bn1b + l * FCO);
        k_edgeD<<<DGRID, 256>>>();
        k_red2<<<AFL, 256>>>(bn2g + l * AFL, bn2b + l * AFL);
        k_update_pool<<<N_NODES / 8, 512>>>(ppW, ppb, out, bs);
    }
}

// round 5
// speedup vs baseline: 1.6724x; 1.0074x over previous
#include <cuda_runtime.h>
#include <cuda_bf16.h>
#include <cstdint>

#define N_NODES 51200
#define N_EDGES 614400
#define ORIG    92
#define AFL     64
#define BINS    100
#define NCONV   3
#define TBL     128
#define FCO     128      // 2*AFL
#define EPS_BN  1e-5f
#define EGRID   1024
#define DGRID   1024
#define PROJ_ROWS 64
#define HPAD    68

// ---------------- device scratch (static, no allocations) ----------------
__device__ float g_h[N_NODES * AFL];
__device__ float g_Zd[N_NODES * FCO];
__device__ float g_Zs[N_NODES * FCO];
__device__ float g_T[TBL * FCO];              // 64 KB lookup table
__device__ float g_aggr[N_NODES * AFL];
__device__ float g_part1[EGRID * 256];
__device__ float g_part2[DGRID * 128];
__device__ float g_bn1sc[FCO], g_bn1sh[FCO];
__device__ float g_bn2sc[AFL], g_bn2sh[AFL];
__device__ int   g_cnt[N_NODES];
__device__ int   g_segstart[N_NODES + 1];
__device__ int   g_off[N_NODES];
__device__ int   g_psrc[N_EDGES];
__device__ float g_pattr[N_EDGES];

// ---------------- zero out + cnt ----------------
__global__ void k_zero(float* __restrict__ out, int n) {
    int i = blockIdx.x * blockDim.x + threadIdx.x;
    int stride = gridDim.x * blockDim.x;
    for (int j = i; j < n; j += stride) out[j] = 0.f;
    for (int j = i; j < N_NODES; j += stride) g_cnt[j] = 0;
}

// ---------------- embedding + initial pooling (8 nodes/block) ----------------
__global__ void __launch_bounds__(512) k_embed_pool(
    const float* __restrict__ x, const float* __restrict__ att,
    const float* __restrict__ W, const float* __restrict__ b,
    const float* __restrict__ ppW, const float* __restrict__ ppb,
    float* __restrict__ out, const int* __restrict__ bs)
{
    __shared__ float Ws[ORIG * AFL];
    __shared__ float ppWs[AFL * AFL];
    __shared__ float xs[8][ORIG];
    __shared__ float hs[8][AFL];
    __shared__ float red[16];
    __shared__ float bsum[AFL];
    int tid = threadIdx.x;
    int g = tid >> 6, c = tid & 63;
    int n = blockIdx.x * 8 + g;
    for (int i = tid; i < ORIG * AFL; i += 512) Ws[i] = W[i];
    for (int i = tid; i < AFL * AFL; i += 512) ppWs[i] = ppW[i];
    for (int i = tid; i < 8 * ORIG; i += 512) {
        int gg = i / ORIG, k = i - gg * ORIG;
        xs[gg][k] = x[(blockIdx.x * 8 + gg) * ORIG + k] * att[k];
    }
    if (tid < AFL) bsum[tid] = 0.f;
    __syncthreads();
    float acc = b[c];
#pragma unroll 4
    for (int k = 0; k < ORIG; k++) acc = fmaf(xs[g][k], Ws[k * AFL + c], acc);
    g_h[n * AFL + c] = acc;
    hs[g][c] = acc;
    __syncthreads();
    float p = ppb[c];
#pragma unroll 8
    for (int k = 0; k < AFL; k++) p = fmaf(hs[g][k], ppWs[k * AFL + c], p);
    int wid = tid >> 5;
    float m = p;
#pragma unroll
    for (int o = 16; o; o >>= 1) m = fmaxf(m, __shfl_xor_sync(0xffffffffu, m, o));
    if ((tid & 31) == 0) red[wid] = m;
    __syncthreads();
    m = fmaxf(red[g * 2], red[g * 2 + 1]);
    float ex = expf(p - m);
    float s = ex;
#pragma unroll
    for (int o = 16; o; o >>= 1) s += __shfl_xor_sync(0xffffffffu, s, o);
    __syncthreads();
    if ((tid & 31) == 0) red[wid] = s;
    __syncthreads();
    s = red[g * 2] + red[g * 2 + 1];
    int numAtom = N_NODES / bs[0];
    float val = ex / s;
    int n0 = blockIdx.x * 8;
    if (n0 / numAtom == (n0 + 7) / numAtom) {
        atomicAdd(&bsum[c], val);
        __syncthreads();
        if (tid < AFL) atomicAdd(&out[(n0 / numAtom) * AFL + tid], bsum[tid]);
    } else {
        atomicAdd(&out[(n / numAtom) * AFL + c], val);
    }
}

// ---------------- fused table ----------------
__global__ void __launch_bounds__(FCO) k_table(
    const float* __restrict__ w1, const float* __restrict__ b1,
    const float* __restrict__ w2, const float* __restrict__ b2,
    const float* __restrict__ alpha, const float* __restrict__ lut,
    const float* __restrict__ fcW, const float* __restrict__ fcb)
{
    __shared__ float v2[BINS];
    __shared__ float p[BINS];
    __shared__ float q[AFL];
    __shared__ float redA[4];
    __shared__ float redB[4];
    int tid = threadIdx.x;
    float a = (float)blockIdx.x / (float)(TBL - 1);
    if (tid < BINS) {
        float v = fmaf(a, w1[tid], b1[tid]);
        v2[tid] = v > 0.f ? v : 0.01f * v;
    }
    __syncthreads();
    float v3 = -3.0e38f;
    if (tid < BINS) {
        float acc = fmaf(alpha[0], v2[tid], b2[tid]);
#pragma unroll 4
        for (int k = 0; k < BINS; k++) acc = fmaf(v2[k], w2[k * BINS + tid], acc);
        v3 = acc;
    }
    float m = v3;
#pragma unroll
    for (int o = 16; o; o >>= 1) m = fmaxf(m, __shfl_xor_sync(0xffffffffu, m, o));
    if ((tid & 31) == 0) redA[tid >> 5] = m;
    __syncthreads();
    m = fmaxf(fmaxf(redA[0], redA[1]), fmaxf(redA[2], redA[3]));
    float ex = (tid < BINS) ? expf(v3 - m) : 0.f;
    float s = ex;
#pragma unroll
    for (int o = 16; o; o >>= 1) s += __shfl_xor_sync(0xffffffffu, s, o);
    if ((tid & 31) == 0) redB[tid >> 5] = s;
    __syncthreads();
    s = (redB[0] + redB[1]) + (redB[2] + redB[3]);
    float inv = 1.f / s;
    if (tid < BINS) p[tid] = ex * inv;
    __syncthreads();
    if (tid < AFL) {
        float acc = 0.f;
#pragma unroll 4
        for (int j = 0; j < BINS; j++) acc = fmaf(p[j], lut[j * AFL + tid], acc);
        q[tid] = acc;
    }
    __syncthreads();
    float acc = fcb[tid];
#pragma unroll 4
    for (int mm = 0; mm < AFL; mm++)
        acc = fmaf(q[mm], fcW[(2 * AFL + mm) * FCO + tid], acc);
    g_T[blockIdx.x * FCO + tid] = acc;
}

// ---------------- node projections: register prefetch of W chunks ----------------
__global__ void __launch_bounds__(256) k_proj(const float* __restrict__ fcW)
{
    __shared__ float Wsh[16 * 256];           // 16 KB
    __shared__ float hsh[AFL * HPAD];         // 17.4 KB
    int tid = threadIdx.x;
    int tx = tid & 63;
    int ty = tid >> 6;
    int r0 = blockIdx.x * PROJ_ROWS;
    int col = 4 * tx;

    for (int i = tid; i < PROJ_ROWS * AFL; i += 256) {
        int r = i >> 6, k = i & 63;
        hsh[k * HPAD + r] = g_h[(size_t)(r0 + r) * AFL + k];
    }

    const float4* fcW4 = reinterpret_cast<const float4*>(fcW);
    float4 wpre[4];
#define LOADW(KC)                                                         \
    _Pragma("unroll")                                                     \
    for (int q = 0; q < 4; q++) {                                         \
        int sIdx = tid + q * 256;                                         \
        int kk = sIdx >> 6;                                               \
        int f4 = sIdx & 63;                                               \
        int h2 = f4 >> 5, c24 = f4 & 31;                                  \
        wpre[q] = __ldg(&fcW4[(size_t)(h2 * AFL + (KC) * 16 + kk) * 32 + c24]); \
    }
    LOADW(0);

    float4 acc[16];
#pragma unroll
    for (int r = 0; r < 16; r++) acc[r] = make_float4(0.f, 0.f, 0.f, 0.f);

    for (int kc = 0; kc < 4; kc++) {
        __syncthreads();
#pragma unroll
        for (int q = 0; q < 4; q++)
            reinterpret_cast<float4*>(Wsh)[tid + q * 256] = wpre[q];
        __syncthreads();
        if (kc < 3) { LOADW(kc + 1); }
#pragma unroll
        for (int kk = 0; kk < 16; kk++) {
            float4 w4 = *reinterpret_cast<const float4*>(&Wsh[kk * 256 + col]);
            const float* hrow = &hsh[(kc * 16 + kk) * HPAD + ty * 16];
#pragma unroll
            for (int i = 0; i < 4; i++) {
                float4 h4 = *reinterpret_cast<const float4*>(hrow + 4 * i);
                acc[4 * i + 0].x = fmaf(h4.x, w4.x, acc[4 * i + 0].x);
                acc[4 * i + 0].y = fmaf(h4.x, w4.y, acc[4 * i + 0].y);
                acc[4 * i + 0].z = fmaf(h4.x, w4.z, acc[4 * i + 0].z);
                acc[4 * i + 0].w = fmaf(h4.x, w4.w, acc[4 * i + 0].w);
                acc[4 * i + 1].x = fmaf(h4.y, w4.x, acc[4 * i + 1].x);
                acc[4 * i + 1].y = fmaf(h4.y, w4.y, acc[4 * i + 1].y);
                acc[4 * i + 1].z = fmaf(h4.y, w4.z, acc[4 * i + 1].z);
                acc[4 * i + 1].w = fmaf(h4.y, w4.w, acc[4 * i + 1].w);
                acc[4 * i + 2].x = fmaf(h4.z, w4.x, acc[4 * i + 2].x);
                acc[4 * i + 2].y = fmaf(h4.z, w4.y, acc[4 * i + 2].y);
                acc[4 * i + 2].z = fmaf(h4.z, w4.z, acc[4 * i + 2].z);
                acc[4 * i + 2].w = fmaf(h4.z, w4.w, acc[4 * i + 2].w);
                acc[4 * i + 3].x = fmaf(h4.w, w4.x, acc[4 * i + 3].x);
                acc[4 * i + 3].y = fmaf(h4.w, w4.y, acc[4 * i + 3].y);
                acc[4 * i + 3].z = fmaf(h4.w, w4.z, acc[4 * i + 3].z);
                acc[4 * i + 3].w = fmaf(h4.w, w4.w, acc[4 * i + 3].w);
            }
        }
    }
#undef LOADW
    int half = col >> 7;
    int cc = col & 127;
    float* dst = half ? g_Zs : g_Zd;
#pragma unroll
    for (int r = 0; r < 16; r++)
        *reinterpret_cast<float4*>(&dst[(size_t)(r0 + ty * 16 + r) * FCO + cc]) = acc[r];
}

// ---------------- edge sort ----------------
__global__ void __launch_bounds__(1024) k_hist(const int* __restrict__ ei) {
    int e = blockIdx.x * blockDim.x + threadIdx.x;
    if (e < N_EDGES) atomicAdd(&g_cnt[ei[N_EDGES + e]], 1);
}

__global__ void __launch_bounds__(1024) k_scan() {
    __shared__ int wsum[32];
    __shared__ int carry;
    int tid = threadIdx.x;
    int lane = tid & 31, wid = tid >> 5;
    if (tid == 0) carry = 0;
    __syncthreads();
    for (int base = 0; base < N_NODES; base += 1024) {
        int v = g_cnt[base + tid];
        int x = v;
#pragma unroll
        for (int o = 1; o < 32; o <<= 1) {
            int t = __shfl_up_sync(0xffffffffu, x, o);
            if (lane >= o) x += t;
        }
        if (lane == 31) wsum[wid] = x;
        __syncthreads();
        if (wid == 0) {
            int sv = wsum[lane];
#pragma unroll
            for (int o = 1; o < 32; o <<= 1) {
                int t = __shfl_up_sync(0xffffffffu, sv, o);
                if (lane >= o) sv += t;
            }
            wsum[lane] = sv;
        }
        __syncthreads();
        int woff = (wid > 0) ? wsum[wid - 1] : 0;
        int ex = carry + woff + x - v;
        g_segstart[base + tid] = ex;
        g_off[base + tid] = ex;
        __syncthreads();
        if (tid == 0) carry += wsum[31];
        __syncthreads();
    }
    if (tid == 0) g_segstart[N_NODES] = N_EDGES;
}

__global__ void __launch_bounds__(1024) k_scatter(const int* __restrict__ ei,
                                                  const float* __restrict__ ea) {
    int e = blockIdx.x * blockDim.x + threadIdx.x;
    if (e < N_EDGES) {
        int dst = ei[N_EDGES + e];
        int pos = atomicAdd(&g_off[dst], 1);
        g_psrc[pos] = ei[e];
        g_pattr[pos] = ea[e];
    }
}

// ---------------- pass C: BN1 stats, half-warp per edge ----------------
__global__ void __launch_bounds__(256) k_edgeC()
{
    __shared__ float sred[16 * 256];   // 16 KB
    int tid = threadIdx.x;
    int warp = tid >> 5, lane = tid & 31;
    int cl = lane & 15, eh = lane >> 4;
    int slice = warp * 2 + eh;
    int gw = blockIdx.x * 8 + warp;
    int nw = gridDim.x * 8;
    const float4* T4 = reinterpret_cast<const float4*>(g_T);
    float4 ps0 = {0,0,0,0}, pq0 = {0,0,0,0};
    float4 ps1 = {0,0,0,0}, pq1 = {0,0,0,0};

    for (int n = gw; n < N_NODES; n += nw) {
        int beg = g_segstart[n], end = g_segstart[n + 1];
        if (beg == end) continue;
        const float4* zdp = reinterpret_cast<const float4*>(&g_Zd[(size_t)n * FCO]);
        float4 zd0 = __ldg(zdp + cl), zd1 = __ldg(zdp + 16 + cl);

        auto doedge = [&](const float4& zs0, const float4& zs1, float a) {
            float pos = fminf(fmaxf(a * (float)(TBL - 1), 0.f), (float)(TBL - 1));
            int t0 = min((int)pos, TBL - 2);
            float w = pos - (float)t0;
            float4 T0l = __ldg(T4 + t0 * 32 + cl);
            float4 T0h = __ldg(T4 + t0 * 32 + 16 + cl);
            float4 T1l = __ldg(T4 + (t0 + 1) * 32 + cl);
            float4 T1h = __ldg(T4 + (t0 + 1) * 32 + 16 + cl);
            float4 z0, z1;
            z0.x = zd0.x + zs0.x + fmaf(w, T1l.x - T0l.x, T0l.x);
            z0.y = zd0.y + zs0.y + fmaf(w, T1l.y - T0l.y, T0l.y);
            z0.z = zd0.z + zs0.z + fmaf(w, T1l.z - T0l.z, T0l.z);
            z0.w = zd0.w + zs0.w + fmaf(w, T1l.w - T0l.w, T0l.w);
            z1.x = zd1.x + zs1.x + fmaf(w, T1h.x - T0h.x, T0h.x);
            z1.y = zd1.y + zs1.y + fmaf(w, T1h.y - T0h.y, T0h.y);
            z1.z = zd1.z + zs1.z + fmaf(w, T1h.z - T0h.z, T0h.z);
            z1.w = zd1.w + zs1.w + fmaf(w, T1h.w - T0h.w, T0h.w);
            ps0.x += z0.x; ps0.y += z0.y; ps0.z += z0.z; ps0.w += z0.w;
            pq0.x = fmaf(z0.x, z0.x, pq0.x); pq0.y = fmaf(z0.y, z0.y, pq0.y);
            pq0.z = fmaf(z0.z, z0.z, pq0.z); pq0.w = fmaf(z0.w, z0.w, pq0.w);
            ps1.x += z1.x; ps1.y += z1.y; ps1.z += z1.z; ps1.w += z1.w;
            pq1.x = fmaf(z1.x, z1.x, pq1.x); pq1.y = fmaf(z1.y, z1.y, pq1.y);
            pq1.z = fmaf(z1.z, z1.z, pq1.z); pq1.w = fmaf(z1.w, z1.w, pq1.w);
        };

        for (int base = beg; base < end; base += 32) {
            int e = base + lane;
            int sv = 0; float av = 0.f;
            if (e < end) { sv = g_psrc[e]; av = g_pattr[e]; }
            int cnt = min(32, end - base);
            int j = 0;
            for (; j + 4 <= cnt; j += 4) {
                int iA = j + eh, iB = j + 2 + eh;
                int sA = __shfl_sync(0xffffffffu, sv, iA);
                int sB = __shfl_sync(0xffffffffu, sv, iB);
                float aA = __shfl_sync(0xffffffffu, av, iA);
                float aB = __shfl_sync(0xffffffffu, av, iB);
                const float4* zA = reinterpret_cast<const float4*>(&g_Zs[(size_t)sA * FCO]);
                const float4* zB = reinterpret_cast<const float4*>(&g_Zs[(size_t)sB * FCO]);
                float4 zA0 = __ldg(zA + cl), zA1 = __ldg(zA + 16 + cl);
                float4 zB0 = __ldg(zB + cl), zB1 = __ldg(zB + 16 + cl);
                doedge(zA0, zA1, aA);
                doedge(zB0, zB1, aB);
            }
            for (; j + 2 <= cnt; j += 2) {
                int iA = j + eh;
                int sA = __shfl_sync(0xffffffffu, sv, iA);
                float aA = __shfl_sync(0xffffffffu, av, iA);
                const float4* zA = reinterpret_cast<const float4*>(&g_Zs[(size_t)sA * FCO]);
                float4 zA0 = __ldg(zA + cl), zA1 = __ldg(zA + 16 + cl);
                doedge(zA0, zA1, aA);
            }
            if (j < cnt) {
                int sA = __shfl_sync(0xffffffffu, sv, j);
                float aA = __shfl_sync(0xffffffffu, av, j);
                if (eh == 0) {
                    const float4* zA = reinterpret_cast<const float4*>(&g_Zs[(size_t)sA * FCO]);
                    float4 zA0 = __ldg(zA + cl), zA1 = __ldg(zA + 16 + cl);
                    doedge(zA0, zA1, aA);
                }
            }
        }
    }
    {
        float* sb = &sred[slice * 256];
        int c4 = cl * 4;
        sb[c4 + 0] = ps0.x; sb[c4 + 1] = ps0.y; sb[c4 + 2] = ps0.z; sb[c4 + 3] = ps0.w;
        sb[64 + c4 + 0] = ps1.x; sb[64 + c4 + 1] = ps1.y; sb[64 + c4 + 2] = ps1.z; sb[64 + c4 + 3] = ps1.w;
        sb[128 + c4 + 0] = pq0.x; sb[128 + c4 + 1] = pq0.y; sb[128 + c4 + 2] = pq0.z; sb[128 + c4 + 3] = pq0.w;
        sb[192 + c4 + 0] = pq1.x; sb[192 + c4 + 1] = pq1.y; sb[192 + c4 + 2] = pq1.z; sb[192 + c4 + 3] = pq1.w;
    }
    __syncthreads();
    float v = 0.f;
#pragma unroll
    for (int s = 0; s < 16; s++) v += sred[s * 256 + tid];
    g_part1[blockIdx.x * 256 + tid] = v;
}

__global__ void __launch_bounds__(256) k_red1(
    const float* __restrict__ g1, const float* __restrict__ b1)
{
    __shared__ float ssum[256], ssq[256];
    int c = blockIdx.x;
    int t = threadIdx.x;
    float s = 0.f, q = 0.f;
    for (int r = t; r < EGRID; r += 256) {
        s += g_part1[r * 256 + c];
        q += g_part1[r * 256 + 128 + c];
    }
    ssum[t] = s; ssq[t] = q;
    __syncthreads();
    for (int o = 128; o; o >>= 1) {
        if (t < o) { ssum[t] += ssum[t + o]; ssq[t] += ssq[t + o]; }
        __syncthreads();
    }
    if (t == 0) {
        const float invE = 1.f / (float)N_EDGES;
        float mu = ssum[0] * invE;
        float var = ssq[0] * invE - mu * mu;
        float sc = rsqrtf(var + EPS_BN) * g1[c];
        g_bn1sc[c] = sc;
        g_bn1sh[c] = fmaf(-mu, sc, b1[c]);
    }
}

// ---------------- pass D: message + segment sum + BN2 stats ----------------
__global__ void __launch_bounds__(256) k_edgeD()
{
    __shared__ float sred[8 * 128];
    int tid = threadIdx.x;
    int warp = tid >> 5, lane = tid & 31;
    int cl = lane & 15, eh = lane >> 4;
    int gw = blockIdx.x * 8 + warp;
    int nw = gridDim.x * 8;
    const float4* T4 = reinterpret_cast<const float4*>(g_T);
    float4 sc0 = reinterpret_cast<const float4*>(g_bn1sc)[cl];
    float4 sc1 = reinterpret_cast<const float4*>(g_bn1sc)[16 + cl];
    float4 sh0 = reinterpret_cast<const float4*>(g_bn1sh)[cl];
    float4 sh1 = reinterpret_cast<const float4*>(g_bn1sh)[16 + cl];
    float4 ps = {0,0,0,0}, pq = {0,0,0,0};

    for (int n = gw; n < N_NODES; n += nw) {
        int beg = g_segstart[n], end = g_segstart[n + 1];
        float4 acc = {0,0,0,0};
        if (beg < end) {
            const float4* zdp = reinterpret_cast<const float4*>(&g_Zd[(size_t)n * FCO]);
            float4 zd0 = __ldg(zdp + cl), zd1 = __ldg(zdp + 16 + cl);

            auto doedge = [&](const float4& zs0, const float4& zs1, float a) {
                float pos = fminf(fmaxf(a * (float)(TBL - 1), 0.f), (float)(TBL - 1));
                int t0 = min((int)pos, TBL - 2);
                float w = pos - (float)t0;
                float4 T0l = __ldg(T4 + t0 * 32 + cl);
                float4 T0h = __ldg(T4 + t0 * 32 + 16 + cl);
                float4 T1l = __ldg(T4 + (t0 + 1) * 32 + cl);
                float4 T1h = __ldg(T4 + (t0 + 1) * 32 + 16 + cl);
                float4 z0, z1;
                z0.x = zd0.x + zs0.x + fmaf(w, T1l.x - T0l.x, T0l.x);
                z0.y = zd0.y + zs0.y + fmaf(w, T1l.y - T0l.y, T0l.y);
                z0.z = zd0.z + zs0.z + fmaf(w, T1l.z - T0l.z, T0l.z);
                z0.w = zd0.w + zs0.w + fmaf(w, T1l.w - T0l.w, T0l.w);
                z1.x = zd1.x + zs1.x + fmaf(w, T1h.x - T0h.x, T0h.x);
                z1.y = zd1.y + zs1.y + fmaf(w, T1h.y - T0h.y, T0h.y);
                z1.z = zd1.z + zs1.z + fmaf(w, T1h.z - T0h.z, T0h.z);
                z1.w = zd1.w + zs1.w + fmaf(w, T1h.w - T0h.w, T0h.w);
                float fx = fmaxf(fmaf(z0.x, sc0.x, sh0.x), 0.f);
                float fy = fmaxf(fmaf(z0.y, sc0.y, sh0.y), 0.f);
                float fz = fmaxf(fmaf(z0.z, sc0.z, sh0.z), 0.f);
                float fw = fmaxf(fmaf(z0.w, sc0.w, sh0.w), 0.f);
                float gx = fmaxf(fmaf(z1.x, sc1.x, sh1.x), 0.f);
                float gy = fmaxf(fmaf(z1.y, sc1.y, sh1.y), 0.f);
                float gz = fmaxf(fmaf(z1.z, sc1.z, sh1.z), 0.f);
                float gw2 = fmaxf(fmaf(z1.w, sc1.w, sh1.w), 0.f);
                acc.x = fmaf(fx, gx, acc.x);
                acc.y = fmaf(fy, gy, acc.y);
                acc.z = fmaf(fz, gz, acc.z);
                acc.w = fmaf(fw, gw2, acc.w);
            };

            for (int base = beg; base < end; base += 32) {
                int e = base + lane;
                int sv = 0; float av = 0.f;
                if (e < end) { sv = g_psrc[e]; av = g_pattr[e]; }
                int cnt = min(32, end - base);
                int j = 0;
                for (; j + 4 <= cnt; j += 4) {
                    int iA = j + eh, iB = j + 2 + eh;
                    int sA = __shfl_sync(0xffffffffu, sv, iA);
                    int sB = __shfl_sync(0xffffffffu, sv, iB);
                    float aA = __shfl_sync(0xffffffffu, av, iA);
                    float aB = __shfl_sync(0xffffffffu, av, iB);
                    const float4* zA = reinterpret_cast<const float4*>(&g_Zs[(size_t)sA * FCO]);
                    const float4* zB = reinterpret_cast<const float4*>(&g_Zs[(size_t)sB * FCO]);
                    float4 zA0 = __ldg(zA + cl), zA1 = __ldg(zA + 16 + cl);
                    float4 zB0 = __ldg(zB + cl), zB1 = __ldg(zB + 16 + cl);
                    doedge(zA0, zA1, aA);
                    doedge(zB0, zB1, aB);
                }
                for (; j + 2 <= cnt; j += 2) {
                    int iA = j + eh;
                    int sA = __shfl_sync(0xffffffffu, sv, iA);
                    float aA = __shfl_sync(0xffffffffu, av, iA);
                    const float4* zA = reinterpret_cast<const float4*>(&g_Zs[(size_t)sA * FCO]);
                    float4 zA0 = __ldg(zA + cl), zA1 = __ldg(zA + 16 + cl);
                    doedge(zA0, zA1, aA);
                }
                if (j < cnt) {
                    int sA = __shfl_sync(0xffffffffu, sv, j);
                    float aA = __shfl_sync(0xffffffffu, av, j);
                    if (eh == 0) {
                        const float4* zA = reinterpret_cast<const float4*>(&g_Zs[(size_t)sA * FCO]);
                        float4 zA0 = __ldg(zA + cl), zA1 = __ldg(zA + 16 + cl);
                        doedge(zA0, zA1, aA);
                    }
                }
            }
        }
        // combine eh halves (lane <- lane+16), store, accumulate BN2 stats
        acc.x += __shfl_down_sync(0xffffffffu, acc.x, 16);
        acc.y += __shfl_down_sync(0xffffffffu, acc.y, 16);
        acc.z += __shfl_down_sync(0xffffffffu, acc.z, 16);
        acc.w += __shfl_down_sync(0xffffffffu, acc.w, 16);
        if (eh == 0) {
            reinterpret_cast<float4*>(&g_aggr[(size_t)n * AFL])[cl] = acc;
            ps.x += acc.x; ps.y += acc.y; ps.z += acc.z; ps.w += acc.w;
            pq.x = fmaf(acc.x, acc.x, pq.x); pq.y = fmaf(acc.y, acc.y, pq.y);
            pq.z = fmaf(acc.z, acc.z, pq.z); pq.w = fmaf(acc.w, acc.w, pq.w);
        }
    }
    if (eh == 0) {
        float* sb = &sred[warp * 128];
        int c4 = cl * 4;
        sb[c4 + 0] = ps.x; sb[c4 + 1] = ps.y; sb[c4 + 2] = ps.z; sb[c4 + 3] = ps.w;
        sb[64 + c4 + 0] = pq.x; sb[64 + c4 + 1] = pq.y; sb[64 + c4 + 2] = pq.z; sb[64 + c4 + 3] = pq.w;
    }
    __syncthreads();
    if (tid < 128) {
        float v = 0.f;
#pragma unroll
        for (int w = 0; w < 8; w++) v += sred[w * 128 + tid];
        g_part2[blockIdx.x * 128 + tid] = v;
    }
}

__global__ void __launch_bounds__(256) k_red2(
    const float* __restrict__ g2, const float* __restrict__ b2)
{
    __shared__ float ssum[256], ssq[256];
    int c = blockIdx.x;
    int t = threadIdx.x;
    float s = 0.f, q = 0.f;
    for (int r = t; r < DGRID; r += 256) {
        s += g_part2[r * 128 + c];
        q += g_part2[r * 128 + 64 + c];
    }
    ssum[t] = s; ssq[t] = q;
    __syncthreads();
    for (int o = 128; o; o >>= 1) {
        if (t < o) { ssum[t] += ssum[t + o]; ssq[t] += ssq[t + o]; }
        __syncthreads();
    }
    if (t == 0) {
        const float invN = 1.f / (float)N_NODES;
        float mu = ssum[0] * invN;
        float var = ssq[0] * invN - mu * mu;
        float sc = rsqrtf(var + EPS_BN) * g2[c];
        g_bn2sc[c] = sc;
        g_bn2sh[c] = fmaf(-mu, sc, b2[c]);
    }
}

// ---------------- update + pooling (8 nodes/block) ----------------
__global__ void __launch_bounds__(512) k_update_pool(
    const float* __restrict__ ppW, const float* __restrict__ ppb,
    float* __restrict__ out, const int* __restrict__ bs)
{
    __shared__ float ppWs[AFL * AFL];
    __shared__ float hs[8][AFL];
    __shared__ float red[16];
    __shared__ float bsum[AFL];
    int tid = threadIdx.x;
    int g = tid >> 6, c = tid & 63;
    int n = blockIdx.x * 8 + g;
    for (int i = tid; i < AFL * AFL; i += 512) ppWs[i] = ppW[i];
    if (tid < AFL) bsum[tid] = 0.f;
    float up = fmaxf(g_h[n * AFL + c] +
                     fmaf(g_aggr[n * AFL + c], g_bn2sc[c], g_bn2sh[c]), 0.f);
    g_h[n * AFL + c] = up;
    hs[g][c] = up;
    __syncthreads();
    float p = ppb[c];
#pragma unroll 8
    for (int k = 0; k < AFL; k++) p = fmaf(hs[g][k], ppWs[k * AFL + c], p);
    int wid = tid >> 5;
    float m = p;
#pragma unroll
    for (int o = 16; o; o >>= 1) m = fmaxf(m, __shfl_xor_sync(0xffffffffu, m, o));
    if ((tid & 31) == 0) red[wid] = m;
    __syncthreads();
    m = fmaxf(red[g * 2], red[g * 2 + 1]);
    float ex = expf(p - m);
    float s = ex;
#pragma unroll
    for (int o = 16; o; o >>= 1) s += __shfl_xor_sync(0xffffffffu, s, o);
    __syncthreads();
    if ((tid & 31) == 0) red[wid] = s;
    __syncthreads();
    s = red[g * 2] + red[g * 2 + 1];
    int numAtom = N_NODES / bs[0];
    float val = ex / s;
    int n0 = blockIdx.x * 8;
    if (n0 / numAtom == (n0 + 7) / numAtom) {
        atomicAdd(&bsum[c], val);
        __syncthreads();
        if (tid < AFL) atomicAdd(&out[(n0 / numAtom) * AFL + tid], bsum[tid]);
    } else {
        atomicAdd(&out[(n / numAtom) * AFL + c], val);
    }
}

// ---------------- launch ----------------
extern "C" void kernel_launch(void* const* d_in, const int* in_sizes, int n_in,
                              void* d_out, int out_size)
{
    const float* x     = (const float*)d_in[0];
    const int*   ei    = (const int*)  d_in[1];
    const float* ea    = (const float*)d_in[2];
    const int*   bs    = (const int*)  d_in[3];
    const float* att   = (const float*)d_in[4];
    const float* embW  = (const float*)d_in[5];
    const float* embb  = (const float*)d_in[6];
    const float* adw1  = (const float*)d_in[7];
    const float* adb1  = (const float*)d_in[8];
    const float* adw2  = (const float*)d_in[9];
    const float* adb2  = (const float*)d_in[10];
    const float* adal  = (const float*)d_in[11];
    const float* adlut = (const float*)d_in[12];
    const float* fcW   = (const float*)d_in[13];
    const float* fcb   = (const float*)d_in[14];
    const float* bn1g  = (const float*)d_in[15];
    const float* bn1b  = (const float*)d_in[16];
    const float* bn2g  = (const float*)d_in[17];
    const float* bn2b  = (const float*)d_in[18];
    const float* ppW   = (const float*)d_in[19];
    const float* ppb   = (const float*)d_in[20];
    float* out = (float*)d_out;

    k_zero<<<64, 256>>>(out, out_size);
    k_embed_pool<<<N_NODES / 8, 512>>>(x, att, embW, embb, ppW, ppb, out, bs);
    k_table<<<TBL, FCO>>>(adw1, adb1, adw2, adb2, adal, adlut, fcW, fcb);
    k_proj<<<N_NODES / PROJ_ROWS, 256>>>(fcW);          // profiler slot (#4)
    k_hist<<<N_EDGES / 1024, 1024>>>(ei);
    k_scan<<<1, 1024>>>();
    k_scatter<<<N_EDGES / 1024, 1024>>>(ei, ea);

    for (int l = 0; l < NCONV; l++) {
        if (l > 0) {
            k_table<<<TBL, FCO>>>(adw1 + l * BINS, adb1 + l * BINS,
                                  adw2 + l * BINS * BINS, adb2 + l * BINS,
                                  adal + l, adlut + l * BINS * AFL,
                                  fcW + l * (3 * AFL) * FCO, fcb + l * FCO);
            k_proj<<<N_NODES / PROJ_ROWS, 256>>>(fcW + l * (3 * AFL) * FCO);
        }
        k_edgeC<<<EGRID, 256>>>();
        k_red1<<<FCO, 256>>>(bn1g + l * FCO, bn1b + l * FCO);
        k_edgeD<<<DGRID, 256>>>();
        k_red2<<<AFL, 256>>>(bn2g + l * AFL, bn2b + l * AFL);
        k_update_pool<<<N_NODES / 8, 512>>>(ppW, ppb, out, bs);
    }
}

// round 6
// speedup vs baseline: 1.6824x; 1.0060x over previous
#include <cuda_runtime.h>
#include <cuda_bf16.h>
#include <cstdint>

#define N_NODES 51200
#define N_EDGES 614400
#define ORIG    92
#define AFL     64
#define BINS    100
#define NCONV   3
#define TBL     128
#define FCO     128      // 2*AFL
#define EPS_BN  1e-5f
#define EGRID   1024
#define DGRID   1024
#define PROJ_ROWS 64
#define HPAD    68

// ---------------- device scratch (static, no allocations) ----------------
__device__ float g_h[N_NODES * AFL];
__device__ float g_Zd[N_NODES * FCO];
__device__ float g_Zs[N_NODES * FCO];
__device__ float g_T[TBL * FCO];              // 64 KB lookup table
__device__ float g_aggr[N_NODES * AFL];
__device__ float g_part1[EGRID * 256];
__device__ float g_part2[DGRID * 128];
__device__ float g_bn1sc[FCO], g_bn1sh[FCO];
__device__ float g_bn2sc[AFL], g_bn2sh[AFL];
__device__ int   g_cnt[N_NODES];
__device__ int   g_segstart[N_NODES + 1];
__device__ int   g_off[N_NODES];
__device__ int   g_psrc[N_EDGES];
__device__ float g_pattr[N_EDGES];

// ---------------- zero out + cnt ----------------
__global__ void k_zero(float* __restrict__ out, int n) {
    int i = blockIdx.x * blockDim.x + threadIdx.x;
    int stride = gridDim.x * blockDim.x;
    for (int j = i; j < n; j += stride) out[j] = 0.f;
    for (int j = i; j < N_NODES; j += stride) g_cnt[j] = 0;
}

// ---------------- embedding + initial pooling (8 nodes/block) ----------------
__global__ void __launch_bounds__(512) k_embed_pool(
    const float* __restrict__ x, const float* __restrict__ att,
    const float* __restrict__ W, const float* __restrict__ b,
    const float* __restrict__ ppW, const float* __restrict__ ppb,
    float* __restrict__ out, const int* __restrict__ bs)
{
    __shared__ float Ws[ORIG * AFL];
    __shared__ float ppWs[AFL * AFL];
    __shared__ float xs[8][ORIG];
    __shared__ float hs[8][AFL];
    __shared__ float red[16];
    __shared__ float bsum[AFL];
    int tid = threadIdx.x;
    int g = tid >> 6, c = tid & 63;
    int n = blockIdx.x * 8 + g;
    for (int i = tid; i < ORIG * AFL; i += 512) Ws[i] = W[i];
    for (int i = tid; i < AFL * AFL; i += 512) ppWs[i] = ppW[i];
    for (int i = tid; i < 8 * ORIG; i += 512) {
        int gg = i / ORIG, k = i - gg * ORIG;
        xs[gg][k] = x[(blockIdx.x * 8 + gg) * ORIG + k] * att[k];
    }
    if (tid < AFL) bsum[tid] = 0.f;
    __syncthreads();
    float acc = b[c];
#pragma unroll 4
    for (int k = 0; k < ORIG; k++) acc = fmaf(xs[g][k], Ws[k * AFL + c], acc);
    g_h[n * AFL + c] = acc;
    hs[g][c] = acc;
    __syncthreads();
    float p = ppb[c];
#pragma unroll 8
    for (int k = 0; k < AFL; k++) p = fmaf(hs[g][k], ppWs[k * AFL + c], p);
    int wid = tid >> 5;
    float m = p;
#pragma unroll
    for (int o = 16; o; o >>= 1) m = fmaxf(m, __shfl_xor_sync(0xffffffffu, m, o));
    if ((tid & 31) == 0) red[wid] = m;
    __syncthreads();
    m = fmaxf(red[g * 2], red[g * 2 + 1]);
    float ex = expf(p - m);
    float s = ex;
#pragma unroll
    for (int o = 16; o; o >>= 1) s += __shfl_xor_sync(0xffffffffu, s, o);
    __syncthreads();
    if ((tid & 31) == 0) red[wid] = s;
    __syncthreads();
    s = red[g * 2] + red[g * 2 + 1];
    int numAtom = N_NODES / bs[0];
    float val = ex / s;
    int n0 = blockIdx.x * 8;
    if (n0 / numAtom == (n0 + 7) / numAtom) {
        atomicAdd(&bsum[c], val);
        __syncthreads();
        if (tid < AFL) atomicAdd(&out[(n0 / numAtom) * AFL + tid], bsum[tid]);
    } else {
        atomicAdd(&out[(n / numAtom) * AFL + c], val);
    }
}

// ---------------- fused table ----------------
__global__ void __launch_bounds__(FCO) k_table(
    const float* __restrict__ w1, const float* __restrict__ b1,
    const float* __restrict__ w2, const float* __restrict__ b2,
    const float* __restrict__ alpha, const float* __restrict__ lut,
    const float* __restrict__ fcW, const float* __restrict__ fcb)
{
    __shared__ float v2[BINS];
    __shared__ float p[BINS];
    __shared__ float q[AFL];
    __shared__ float redA[4];
    __shared__ float redB[4];
    int tid = threadIdx.x;
    float a = (float)blockIdx.x / (float)(TBL - 1);
    if (tid < BINS) {
        float v = fmaf(a, w1[tid], b1[tid]);
        v2[tid] = v > 0.f ? v : 0.01f * v;
    }
    __syncthreads();
    float v3 = -3.0e38f;
    if (tid < BINS) {
        float acc = fmaf(alpha[0], v2[tid], b2[tid]);
#pragma unroll 4
        for (int k = 0; k < BINS; k++) acc = fmaf(v2[k], w2[k * BINS + tid], acc);
        v3 = acc;
    }
    float m = v3;
#pragma unroll
    for (int o = 16; o; o >>= 1) m = fmaxf(m, __shfl_xor_sync(0xffffffffu, m, o));
    if ((tid & 31) == 0) redA[tid >> 5] = m;
    __syncthreads();
    m = fmaxf(fmaxf(redA[0], redA[1]), fmaxf(redA[2], redA[3]));
    float ex = (tid < BINS) ? expf(v3 - m) : 0.f;
    float s = ex;
#pragma unroll
    for (int o = 16; o; o >>= 1) s += __shfl_xor_sync(0xffffffffu, s, o);
    if ((tid & 31) == 0) redB[tid >> 5] = s;
    __syncthreads();
    s = (redB[0] + redB[1]) + (redB[2] + redB[3]);
    float inv = 1.f / s;
    if (tid < BINS) p[tid] = ex * inv;
    __syncthreads();
    if (tid < AFL) {
        float acc = 0.f;
#pragma unroll 4
        for (int j = 0; j < BINS; j++) acc = fmaf(p[j], lut[j * AFL + tid], acc);
        q[tid] = acc;
    }
    __syncthreads();
    float acc = fcb[tid];
#pragma unroll 4
    for (int mm = 0; mm < AFL; mm++)
        acc = fmaf(q[mm], fcW[(2 * AFL + mm) * FCO + tid], acc);
    g_T[blockIdx.x * FCO + tid] = acc;
}

// ---------------- node projections: register-tiled (R4 variant) ----------------
__global__ void __launch_bounds__(256) k_proj(const float* __restrict__ fcW)
{
    __shared__ float Wsh[16 * 256];           // 16 KB
    __shared__ float hsh[AFL * HPAD];         // 17.4 KB
    int tid = threadIdx.x;
    int tx = tid & 63;
    int ty = tid >> 6;
    int r0 = blockIdx.x * PROJ_ROWS;
    int col = 4 * tx;

    for (int i = tid; i < PROJ_ROWS * AFL; i += 256) {
        int r = i >> 6, k = i & 63;
        hsh[k * HPAD + r] = g_h[(size_t)(r0 + r) * AFL + k];
    }

    float4 acc[16];
#pragma unroll
    for (int r = 0; r < 16; r++) acc[r] = make_float4(0.f, 0.f, 0.f, 0.f);

    for (int kc = 0; kc < 4; kc++) {
        __syncthreads();
        for (int i = tid; i < 16 * 256; i += 256) {
            int kk = i >> 8;
            int cl = i & 255;
            int h2 = cl >> 7, c2 = cl & 127;
            Wsh[i] = fcW[(size_t)(h2 * AFL + kc * 16 + kk) * FCO + c2];
        }
        __syncthreads();
#pragma unroll
        for (int kk = 0; kk < 16; kk++) {
            float4 w4 = *reinterpret_cast<const float4*>(&Wsh[kk * 256 + col]);
            const float* hrow = &hsh[(kc * 16 + kk) * HPAD + ty * 16];
#pragma unroll
            for (int i = 0; i < 4; i++) {
                float4 h4 = *reinterpret_cast<const float4*>(hrow + 4 * i);
                acc[4 * i + 0].x = fmaf(h4.x, w4.x, acc[4 * i + 0].x);
                acc[4 * i + 0].y = fmaf(h4.x, w4.y, acc[4 * i + 0].y);
                acc[4 * i + 0].z = fmaf(h4.x, w4.z, acc[4 * i + 0].z);
                acc[4 * i + 0].w = fmaf(h4.x, w4.w, acc[4 * i + 0].w);
                acc[4 * i + 1].x = fmaf(h4.y, w4.x, acc[4 * i + 1].x);
                acc[4 * i + 1].y = fmaf(h4.y, w4.y, acc[4 * i + 1].y);
                acc[4 * i + 1].z = fmaf(h4.y, w4.z, acc[4 * i + 1].z);
                acc[4 * i + 1].w = fmaf(h4.y, w4.w, acc[4 * i + 1].w);
                acc[4 * i + 2].x = fmaf(h4.z, w4.x, acc[4 * i + 2].x);
                acc[4 * i + 2].y = fmaf(h4.z, w4.y, acc[4 * i + 2].y);
                acc[4 * i + 2].z = fmaf(h4.z, w4.z, acc[4 * i + 2].z);
                acc[4 * i + 2].w = fmaf(h4.z, w4.w, acc[4 * i + 2].w);
                acc[4 * i + 3].x = fmaf(h4.w, w4.x, acc[4 * i + 3].x);
                acc[4 * i + 3].y = fmaf(h4.w, w4.y, acc[4 * i + 3].y);
                acc[4 * i + 3].z = fmaf(h4.w, w4.z, acc[4 * i + 3].z);
                acc[4 * i + 3].w = fmaf(h4.w, w4.w, acc[4 * i + 3].w);
            }
        }
    }
    int half = col >> 7;
    int cc = col & 127;
    float* dst = half ? g_Zs : g_Zd;
#pragma unroll
    for (int r = 0; r < 16; r++)
        *reinterpret_cast<float4*>(&dst[(size_t)(r0 + ty * 16 + r) * FCO + cc]) = acc[r];
}

// ---------------- edge sort ----------------
__global__ void __launch_bounds__(1024) k_hist(const int* __restrict__ ei) {
    int e = blockIdx.x * blockDim.x + threadIdx.x;
    if (e < N_EDGES) atomicAdd(&g_cnt[ei[N_EDGES + e]], 1);
}

__global__ void __launch_bounds__(1024) k_scan() {
    __shared__ int wsum[32];
    __shared__ int carry;
    int tid = threadIdx.x;
    int lane = tid & 31, wid = tid >> 5;
    if (tid == 0) carry = 0;
    __syncthreads();
    for (int base = 0; base < N_NODES; base += 1024) {
        int v = g_cnt[base + tid];
        int x = v;
#pragma unroll
        for (int o = 1; o < 32; o <<= 1) {
            int t = __shfl_up_sync(0xffffffffu, x, o);
            if (lane >= o) x += t;
        }
        if (lane == 31) wsum[wid] = x;
        __syncthreads();
        if (wid == 0) {
            int sv = wsum[lane];
#pragma unroll
            for (int o = 1; o < 32; o <<= 1) {
                int t = __shfl_up_sync(0xffffffffu, sv, o);
                if (lane >= o) sv += t;
            }
            wsum[lane] = sv;
        }
        __syncthreads();
        int woff = (wid > 0) ? wsum[wid - 1] : 0;
        int ex = carry + woff + x - v;
        g_segstart[base + tid] = ex;
        g_off[base + tid] = ex;
        __syncthreads();
        if (tid == 0) carry += wsum[31];
        __syncthreads();
    }
    if (tid == 0) g_segstart[N_NODES] = N_EDGES;
}

__global__ void __launch_bounds__(1024) k_scatter(const int* __restrict__ ei,
                                                  const float* __restrict__ ea) {
    int e = blockIdx.x * blockDim.x + threadIdx.x;
    if (e < N_EDGES) {
        int dst = ei[N_EDGES + e];
        int pos = atomicAdd(&g_off[dst], 1);
        g_psrc[pos] = ei[e];
        g_pattr[pos] = ea[e];
    }
}

// ---------------- pass C: BN1 stats, half-warp per edge, 8-wide batches ----------------
__global__ void __launch_bounds__(256) k_edgeC()
{
    __shared__ float sred[16 * 256];   // 16 KB
    int tid = threadIdx.x;
    int warp = tid >> 5, lane = tid & 31;
    int cl = lane & 15, eh = lane >> 4;
    int slice = warp * 2 + eh;
    int gw = blockIdx.x * 8 + warp;
    int nw = gridDim.x * 8;
    const float4* T4 = reinterpret_cast<const float4*>(g_T);
    float4 ps0 = {0,0,0,0}, pq0 = {0,0,0,0};
    float4 ps1 = {0,0,0,0}, pq1 = {0,0,0,0};

    for (int n = gw; n < N_NODES; n += nw) {
        int beg = g_segstart[n], end = g_segstart[n + 1];
        if (beg == end) continue;
        const float4* zdp = reinterpret_cast<const float4*>(&g_Zd[(size_t)n * FCO]);
        float4 zd0 = __ldg(zdp + cl), zd1 = __ldg(zdp + 16 + cl);

        auto doedge = [&](const float4& zs0, const float4& zs1, float a) {
            float pos = fminf(fmaxf(a * (float)(TBL - 1), 0.f), (float)(TBL - 1));
            int t0 = min((int)pos, TBL - 2);
            float w = pos - (float)t0;
            float4 T0l = __ldg(T4 + t0 * 32 + cl);
            float4 T0h = __ldg(T4 + t0 * 32 + 16 + cl);
            float4 T1l = __ldg(T4 + (t0 + 1) * 32 + cl);
            float4 T1h = __ldg(T4 + (t0 + 1) * 32 + 16 + cl);
            float4 z0, z1;
            z0.x = zd0.x + zs0.x + fmaf(w, T1l.x - T0l.x, T0l.x);
            z0.y = zd0.y + zs0.y + fmaf(w, T1l.y - T0l.y, T0l.y);
            z0.z = zd0.z + zs0.z + fmaf(w, T1l.z - T0l.z, T0l.z);
            z0.w = zd0.w + zs0.w + fmaf(w, T1l.w - T0l.w, T0l.w);
            z1.x = zd1.x + zs1.x + fmaf(w, T1h.x - T0h.x, T0h.x);
            z1.y = zd1.y + zs1.y + fmaf(w, T1h.y - T0h.y, T0h.y);
            z1.z = zd1.z + zs1.z + fmaf(w, T1h.z - T0h.z, T0h.z);
            z1.w = zd1.w + zs1.w + fmaf(w, T1h.w - T0h.w, T0h.w);
            ps0.x += z0.x; ps0.y += z0.y; ps0.z += z0.z; ps0.w += z0.w;
            pq0.x = fmaf(z0.x, z0.x, pq0.x); pq0.y = fmaf(z0.y, z0.y, pq0.y);
            pq0.z = fmaf(z0.z, z0.z, pq0.z); pq0.w = fmaf(z0.w, z0.w, pq0.w);
            ps1.x += z1.x; ps1.y += z1.y; ps1.z += z1.z; ps1.w += z1.w;
            pq1.x = fmaf(z1.x, z1.x, pq1.x); pq1.y = fmaf(z1.y, z1.y, pq1.y);
            pq1.z = fmaf(z1.z, z1.z, pq1.z); pq1.w = fmaf(z1.w, z1.w, pq1.w);
        };

        for (int base = beg; base < end; base += 32) {
            int e = base + lane;
            int sv = 0; float av = 0.f;
            if (e < end) { sv = g_psrc[e]; av = g_pattr[e]; }
            int cnt = min(32, end - base);
            int j = 0;
            for (; j + 8 <= cnt; j += 8) {
                int i0 = j + eh, i1 = j + 2 + eh, i2 = j + 4 + eh, i3 = j + 6 + eh;
                int s0 = __shfl_sync(0xffffffffu, sv, i0);
                int s1 = __shfl_sync(0xffffffffu, sv, i1);
                int s2 = __shfl_sync(0xffffffffu, sv, i2);
                int s3 = __shfl_sync(0xffffffffu, sv, i3);
                float a0 = __shfl_sync(0xffffffffu, av, i0);
                float a1 = __shfl_sync(0xffffffffu, av, i1);
                float a2 = __shfl_sync(0xffffffffu, av, i2);
                float a3 = __shfl_sync(0xffffffffu, av, i3);
                const float4* z0p = reinterpret_cast<const float4*>(&g_Zs[(size_t)s0 * FCO]);
                const float4* z1p = reinterpret_cast<const float4*>(&g_Zs[(size_t)s1 * FCO]);
                const float4* z2p = reinterpret_cast<const float4*>(&g_Zs[(size_t)s2 * FCO]);
                const float4* z3p = reinterpret_cast<const float4*>(&g_Zs[(size_t)s3 * FCO]);
                float4 zA0 = __ldg(z0p + cl), zA1 = __ldg(z0p + 16 + cl);
                float4 zB0 = __ldg(z1p + cl), zB1 = __ldg(z1p + 16 + cl);
                float4 zC0 = __ldg(z2p + cl), zC1 = __ldg(z2p + 16 + cl);
                float4 zD0 = __ldg(z3p + cl), zD1 = __ldg(z3p + 16 + cl);
                doedge(zA0, zA1, a0);
                doedge(zB0, zB1, a1);
                doedge(zC0, zC1, a2);
                doedge(zD0, zD1, a3);
            }
            for (; j + 2 <= cnt; j += 2) {
                int iA = j + eh;
                int sA = __shfl_sync(0xffffffffu, sv, iA);
                float aA = __shfl_sync(0xffffffffu, av, iA);
                const float4* zA = reinterpret_cast<const float4*>(&g_Zs[(size_t)sA * FCO]);
                float4 zA0 = __ldg(zA + cl), zA1 = __ldg(zA + 16 + cl);
                doedge(zA0, zA1, aA);
            }
            if (j < cnt) {
                int sA = __shfl_sync(0xffffffffu, sv, j);
                float aA = __shfl_sync(0xffffffffu, av, j);
                if (eh == 0) {
                    const float4* zA = reinterpret_cast<const float4*>(&g_Zs[(size_t)sA * FCO]);
                    float4 zA0 = __ldg(zA + cl), zA1 = __ldg(zA + 16 + cl);
                    doedge(zA0, zA1, aA);
                }
            }
        }
    }
    {
        float* sb = &sred[slice * 256];
        int c4 = cl * 4;
        sb[c4 + 0] = ps0.x; sb[c4 + 1] = ps0.y; sb[c4 + 2] = ps0.z; sb[c4 + 3] = ps0.w;
        sb[64 + c4 + 0] = ps1.x; sb[64 + c4 + 1] = ps1.y; sb[64 + c4 + 2] = ps1.z; sb[64 + c4 + 3] = ps1.w;
        sb[128 + c4 + 0] = pq0.x; sb[128 + c4 + 1] = pq0.y; sb[128 + c4 + 2] = pq0.z; sb[128 + c4 + 3] = pq0.w;
        sb[192 + c4 + 0] = pq1.x; sb[192 + c4 + 1] = pq1.y; sb[192 + c4 + 2] = pq1.z; sb[192 + c4 + 3] = pq1.w;
    }
    __syncthreads();
    float v = 0.f;
#pragma unroll
    for (int s = 0; s < 16; s++) v += sred[s * 256 + tid];
    g_part1[blockIdx.x * 256 + tid] = v;
}

__global__ void __launch_bounds__(256) k_red1(
    const float* __restrict__ g1, const float* __restrict__ b1)
{
    __shared__ float ssum[256], ssq[256];
    int c = blockIdx.x;
    int t = threadIdx.x;
    float s = 0.f, q = 0.f;
    for (int r = t; r < EGRID; r += 256) {
        s += g_part1[r * 256 + c];
        q += g_part1[r * 256 + 128 + c];
    }
    ssum[t] = s; ssq[t] = q;
    __syncthreads();
    for (int o = 128; o; o >>= 1) {
        if (t < o) { ssum[t] += ssum[t + o]; ssq[t] += ssq[t + o]; }
        __syncthreads();
    }
    if (t == 0) {
        const float invE = 1.f / (float)N_EDGES;
        float mu = ssum[0] * invE;
        float var = ssq[0] * invE - mu * mu;
        float sc = rsqrtf(var + EPS_BN) * g1[c];
        g_bn1sc[c] = sc;
        g_bn1sh[c] = fmaf(-mu, sc, b1[c]);
    }
}

// ---------------- pass D: message + segment sum + BN2 stats ----------------
__global__ void __launch_bounds__(256) k_edgeD()
{
    __shared__ float sred[8 * 128];
    int tid = threadIdx.x;
    int warp = tid >> 5, lane = tid & 31;
    int cl = lane & 15, eh = lane >> 4;
    int gw = blockIdx.x * 8 + warp;
    int nw = gridDim.x * 8;
    const float4* T4 = reinterpret_cast<const float4*>(g_T);
    float4 sc0 = reinterpret_cast<const float4*>(g_bn1sc)[cl];
    float4 sc1 = reinterpret_cast<const float4*>(g_bn1sc)[16 + cl];
    float4 sh0 = reinterpret_cast<const float4*>(g_bn1sh)[cl];
    float4 sh1 = reinterpret_cast<const float4*>(g_bn1sh)[16 + cl];
    float4 ps = {0,0,0,0}, pq = {0,0,0,0};

    for (int n = gw; n < N_NODES; n += nw) {
        int beg = g_segstart[n], end = g_segstart[n + 1];
        float4 acc = {0,0,0,0};
        if (beg < end) {
            const float4* zdp = reinterpret_cast<const float4*>(&g_Zd[(size_t)n * FCO]);
            float4 zd0 = __ldg(zdp + cl), zd1 = __ldg(zdp + 16 + cl);

            auto doedge = [&](const float4& zs0, const float4& zs1, float a) {
                float pos = fminf(fmaxf(a * (float)(TBL - 1), 0.f), (float)(TBL - 1));
                int t0 = min((int)pos, TBL - 2);
                float w = pos - (float)t0;
                float4 T0l = __ldg(T4 + t0 * 32 + cl);
                float4 T0h = __ldg(T4 + t0 * 32 + 16 + cl);
                float4 T1l = __ldg(T4 + (t0 + 1) * 32 + cl);
                float4 T1h = __ldg(T4 + (t0 + 1) * 32 + 16 + cl);
                float4 z0, z1;
                z0.x = zd0.x + zs0.x + fmaf(w, T1l.x - T0l.x, T0l.x);
                z0.y = zd0.y + zs0.y + fmaf(w, T1l.y - T0l.y, T0l.y);
                z0.z = zd0.z + zs0.z + fmaf(w, T1l.z - T0l.z, T0l.z);
                z0.w = zd0.w + zs0.w + fmaf(w, T1l.w - T0l.w, T0l.w);
                z1.x = zd1.x + zs1.x + fmaf(w, T1h.x - T0h.x, T0h.x);
                z1.y = zd1.y + zs1.y + fmaf(w, T1h.y - T0h.y, T0h.y);
                z1.z = zd1.z + zs1.z + fmaf(w, T1h.z - T0h.z, T0h.z);
                z1.w = zd1.w + zs1.w + fmaf(w, T1h.w - T0h.w, T0h.w);
                float fx = fmaxf(fmaf(z0.x, sc0.x, sh0.x), 0.f);
                float fy = fmaxf(fmaf(z0.y, sc0.y, sh0.y), 0.f);
                float fz = fmaxf(fmaf(z0.z, sc0.z, sh0.z), 0.f);
                float fw = fmaxf(fmaf(z0.w, sc0.w, sh0.w), 0.f);
                float gx = fmaxf(fmaf(z1.x, sc1.x, sh1.x), 0.f);
                float gy = fmaxf(fmaf(z1.y, sc1.y, sh1.y), 0.f);
                float gz = fmaxf(fmaf(z1.z, sc1.z, sh1.z), 0.f);
                float gw2 = fmaxf(fmaf(z1.w, sc1.w, sh1.w), 0.f);
                acc.x = fmaf(fx, gx, acc.x);
                acc.y = fmaf(fy, gy, acc.y);
                acc.z = fmaf(fz, gz, acc.z);
                acc.w = fmaf(fw, gw2, acc.w);
            };

            for (int base = beg; base < end; base += 32) {
                int e = base + lane;
                int sv = 0; float av = 0.f;
                if (e < end) { sv = g_psrc[e]; av = g_pattr[e]; }
                int cnt = min(32, end - base);
                int j = 0;
                for (; j + 8 <= cnt; j += 8) {
                    int i0 = j + eh, i1 = j + 2 + eh, i2 = j + 4 + eh, i3 = j + 6 + eh;
                    int s0 = __shfl_sync(0xffffffffu, sv, i0);
                    int s1 = __shfl_sync(0xffffffffu, sv, i1);
                    int s2 = __shfl_sync(0xffffffffu, sv, i2);
                    int s3 = __shfl_sync(0xffffffffu, sv, i3);
                    float a0 = __shfl_sync(0xffffffffu, av, i0);
                    float a1 = __shfl_sync(0xffffffffu, av, i1);
                    float a2 = __shfl_sync(0xffffffffu, av, i2);
                    float a3 = __shfl_sync(0xffffffffu, av, i3);
                    const float4* z0p = reinterpret_cast<const float4*>(&g_Zs[(size_t)s0 * FCO]);
                    const float4* z1p = reinterpret_cast<const float4*>(&g_Zs[(size_t)s1 * FCO]);
                    const float4* z2p = reinterpret_cast<const float4*>(&g_Zs[(size_t)s2 * FCO]);
                    const float4* z3p = reinterpret_cast<const float4*>(&g_Zs[(size_t)s3 * FCO]);
                    float4 zA0 = __ldg(z0p + cl), zA1 = __ldg(z0p + 16 + cl);
                    float4 zB0 = __ldg(z1p + cl), zB1 = __ldg(z1p + 16 + cl);
                    float4 zC0 = __ldg(z2p + cl), zC1 = __ldg(z2p + 16 + cl);
                    float4 zD0 = __ldg(z3p + cl), zD1 = __ldg(z3p + 16 + cl);
                    doedge(zA0, zA1, a0);
                    doedge(zB0, zB1, a1);
                    doedge(zC0, zC1, a2);
                    doedge(zD0, zD1, a3);
                }
                for (; j + 2 <= cnt; j += 2) {
                    int iA = j + eh;
                    int sA = __shfl_sync(0xffffffffu, sv, iA);
                    float aA = __shfl_sync(0xffffffffu, av, iA);
                    const float4* zA = reinterpret_cast<const float4*>(&g_Zs[(size_t)sA * FCO]);
                    float4 zA0 = __ldg(zA + cl), zA1 = __ldg(zA + 16 + cl);
                    doedge(zA0, zA1, aA);
                }
                if (j < cnt) {
                    int sA = __shfl_sync(0xffffffffu, sv, j);
                    float aA = __shfl_sync(0xffffffffu, av, j);
                    if (eh == 0) {
                        const float4* zA = reinterpret_cast<const float4*>(&g_Zs[(size_t)sA * FCO]);
                        float4 zA0 = __ldg(zA + cl), zA1 = __ldg(zA + 16 + cl);
                        doedge(zA0, zA1, aA);
                    }
                }
            }
        }
        acc.x += __shfl_down_sync(0xffffffffu, acc.x, 16);
        acc.y += __shfl_down_sync(0xffffffffu, acc.y, 16);
        acc.z += __shfl_down_sync(0xffffffffu, acc.z, 16);
        acc.w += __shfl_down_sync(0xffffffffu, acc.w, 16);
        if (eh == 0) {
            reinterpret_cast<float4*>(&g_aggr[(size_t)n * AFL])[cl] = acc;
            ps.x += acc.x; ps.y += acc.y; ps.z += acc.z; ps.w += acc.w;
            pq.x = fmaf(acc.x, acc.x, pq.x); pq.y = fmaf(acc.y, acc.y, pq.y);
            pq.z = fmaf(acc.z, acc.z, pq.z); pq.w = fmaf(acc.w, acc.w, pq.w);
        }
    }
    if (eh == 0) {
        float* sb = &sred[warp * 128];
        int c4 = cl * 4;
        sb[c4 + 0] = ps.x; sb[c4 + 1] = ps.y; sb[c4 + 2] = ps.z; sb[c4 + 3] = ps.w;
        sb[64 + c4 + 0] = pq.x; sb[64 + c4 + 1] = pq.y; sb[64 + c4 + 2] = pq.z; sb[64 + c4 + 3] = pq.w;
    }
    __syncthreads();
    if (tid < 128) {
        float v = 0.f;
#pragma unroll
        for (int w = 0; w < 8; w++) v += sred[w * 128 + tid];
        g_part2[blockIdx.x * 128 + tid] = v;
    }
}

__global__ void __launch_bounds__(256) k_red2(
    const float* __restrict__ g2, const float* __restrict__ b2)
{
    __shared__ float ssum[256], ssq[256];
    int c = blockIdx.x;
    int t = threadIdx.x;
    float s = 0.f, q = 0.f;
    for (int r = t; r < DGRID; r += 256) {
        s += g_part2[r * 128 + c];
        q += g_part2[r * 128 + 64 + c];
    }
    ssum[t] = s; ssq[t] = q;
    __syncthreads();
    for (int o = 128; o; o >>= 1) {
        if (t < o) { ssum[t] += ssum[t + o]; ssq[t] += ssq[t + o]; }
        __syncthreads();
    }
    if (t == 0) {
        const float invN = 1.f / (float)N_NODES;
        float mu = ssum[0] * invN;
        float var = ssq[0] * invN - mu * mu;
        float sc = rsqrtf(var + EPS_BN) * g2[c];
        g_bn2sc[c] = sc;
        g_bn2sh[c] = fmaf(-mu, sc, b2[c]);
    }
}

// ---------------- update + pooling (8 nodes/block) ----------------
__global__ void __launch_bounds__(512) k_update_pool(
    const float* __restrict__ ppW, const float* __restrict__ ppb,
    float* __restrict__ out, const int* __restrict__ bs)
{
    __shared__ float ppWs[AFL * AFL];
    __shared__ float hs[8][AFL];
    __shared__ float red[16];
    __shared__ float bsum[AFL];
    int tid = threadIdx.x;
    int g = tid >> 6, c = tid & 63;
    int n = blockIdx.x * 8 + g;
    for (int i = tid; i < AFL * AFL; i += 512) ppWs[i] = ppW[i];
    if (tid < AFL) bsum[tid] = 0.f;
    float up = fmaxf(g_h[n * AFL + c] +
                     fmaf(g_aggr[n * AFL + c], g_bn2sc[c], g_bn2sh[c]), 0.f);
    g_h[n * AFL + c] = up;
    hs[g][c] = up;
    __syncthreads();
    float p = ppb[c];
#pragma unroll 8
    for (int k = 0; k < AFL; k++) p = fmaf(hs[g][k], ppWs[k * AFL + c], p);
    int wid = tid >> 5;
    float m = p;
#pragma unroll
    for (int o = 16; o; o >>= 1) m = fmaxf(m, __shfl_xor_sync(0xffffffffu, m, o));
    if ((tid & 31) == 0) red[wid] = m;
    __syncthreads();
    m = fmaxf(red[g * 2], red[g * 2 + 1]);
    float ex = expf(p - m);
    float s = ex;
#pragma unroll
    for (int o = 16; o; o >>= 1) s += __shfl_xor_sync(0xffffffffu, s, o);
    __syncthreads();
    if ((tid & 31) == 0) red[wid] = s;
    __syncthreads();
    s = red[g * 2] + red[g * 2 + 1];
    int numAtom = N_NODES / bs[0];
    float val = ex / s;
    int n0 = blockIdx.x * 8;
    if (n0 / numAtom == (n0 + 7) / numAtom) {
        atomicAdd(&bsum[c], val);
        __syncthreads();
        if (tid < AFL) atomicAdd(&out[(n0 / numAtom) * AFL + tid], bsum[tid]);
    } else {
        atomicAdd(&out[(n / numAtom) * AFL + c], val);
    }
}

// ---------------- launch ----------------
extern "C" void kernel_launch(void* const* d_in, const int* in_sizes, int n_in,
                              void* d_out, int out_size)
{
    const float* x     = (const float*)d_in[0];
    const int*   ei    = (const int*)  d_in[1];
    const float* ea    = (const float*)d_in[2];
    const int*   bs    = (const int*)  d_in[3];
    const float* att   = (const float*)d_in[4];
    const float* embW  = (const float*)d_in[5];
    const float* embb  = (const float*)d_in[6];
    const float* adw1  = (const float*)d_in[7];
    const float* adb1  = (const float*)d_in[8];
    const float* adw2  = (const float*)d_in[9];
    const float* adb2  = (const float*)d_in[10];
    const float* adal  = (const float*)d_in[11];
    const float* adlut = (const float*)d_in[12];
    const float* fcW   = (const float*)d_in[13];
    const float* fcb   = (const float*)d_in[14];
    const float* bn1g  = (const float*)d_in[15];
    const float* bn1b  = (const float*)d_in[16];
    const float* bn2g  = (const float*)d_in[17];
    const float* bn2b  = (const float*)d_in[18];
    const float* ppW   = (const float*)d_in[19];
    const float* ppb   = (const float*)d_in[20];
    float* out = (float*)d_out;

    k_zero<<<64, 256>>>(out, out_size);
    k_embed_pool<<<N_NODES / 8, 512>>>(x, att, embW, embb, ppW, ppb, out, bs);
    k_table<<<TBL, FCO>>>(adw1, adb1, adw2, adb2, adal, adlut, fcW, fcb);
    k_proj<<<N_NODES / PROJ_ROWS, 256>>>(fcW);
    k_hist<<<N_EDGES / 1024, 1024>>>(ei);
    k_scan<<<1, 1024>>>();
    k_scatter<<<N_EDGES / 1024, 1024>>>(ei, ea);

    for (int l = 0; l < NCONV; l++) {
        if (l > 0) {
            k_table<<<TBL, FCO>>>(adw1 + l * BINS, adb1 + l * BINS,
                                  adw2 + l * BINS * BINS, adb2 + l * BINS,
                                  adal + l, adlut + l * BINS * AFL,
                                  fcW + l * (3 * AFL) * FCO, fcb + l * FCO);
            k_proj<<<N_NODES / PROJ_ROWS, 256>>>(fcW + l * (3 * AFL) * FCO);
        }
        k_edgeC<<<EGRID, 256>>>();
        k_red1<<<FCO, 256>>>(bn1g + l * FCO, bn1b + l * FCO);
        k_edgeD<<<DGRID, 256>>>();
        k_red2<<<AFL, 256>>>(bn2g + l * AFL, bn2b + l * AFL);
        k_update_pool<<<N_NODES / 8, 512>>>(ppW, ppb, out, bs);
    }
}